// round 3
// baseline (speedup 1.0000x reference)
#include <cuda_runtime.h>
#include <math.h>

#define NUM_ENVS 16384
#define NUM_AGENTS 16
#define IN_DIM 128
#define GCN_H 64
#define RNN_H 64
#define E_PER_GRAPH 128
#define OUT_DIM 512                   // 16*4*8
#define FLAT_H (NUM_AGENTS * RNN_H)   // 1024

typedef unsigned long long ull;

// Scratch (static device globals — no allocation allowed)
__device__ float  g_hbuf[(size_t)NUM_ENVS * FLAT_H];   // fallback h_new buffer
__device__ float2 g_Wpk[RNN_H * 3 * RNN_H];            // [k][192] = (W_ih[g][k], W_hh[g][k])
__device__ float2 g_Wgp[(IN_DIM / 2) * GCN_H];         // [k2][64] = (Wg[2k2][j], Wg[2k2+1][j])

// ---------------------------------------------------------------------------
// FFMA2 helpers (fma.rn.f32x2 — Blackwell packed fp32 FMA, exact fp32)
// ---------------------------------------------------------------------------
__device__ __forceinline__ void ffma2(ull& d, ull a, ull b) {
    asm("fma.rn.f32x2 %0, %1, %2, %0;" : "+l"(d) : "l"(a), "l"(b));
}
__device__ __forceinline__ ull bcast2(float v) {
    ull r; asm("mov.b64 %0, {%1, %1};" : "=l"(r) : "f"(v)); return r;
}
__device__ __forceinline__ ull pack2(float lo, float hi) {
    ull r; asm("mov.b64 %0, {%1, %2};" : "=l"(r) : "f"(lo), "f"(hi)); return r;
}
__device__ __forceinline__ float2 unpack2(ull u) {
    float2 f; asm("mov.b64 {%0, %1}, %2;" : "=f"(f.x), "=f"(f.y) : "l"(u)); return f;
}

// ---------------------------------------------------------------------------
// Pack weights:
//   Wpk[k*192+g] = (W_ih[g][k], W_hh[g][k])          (GRU lane pairing)
//   Wgp[k2*64+j] = (Wg[2k2][j], Wg[2k2+1][j])        (GCN k-pair pairing)
// ---------------------------------------------------------------------------
__global__ void pack_w_kernel(const float* __restrict__ W_ih,
                              const float* __restrict__ W_hh,
                              const float* __restrict__ Wg) {
    int idx = blockIdx.x * 256 + threadIdx.x;
    if (idx < RNN_H * 192) {
        int k = idx / 192;
        int g = idx % 192;
        g_Wpk[idx] = make_float2(W_ih[g * RNN_H + k], W_hh[g * RNN_H + k]);
    } else if (idx < RNN_H * 192 + (IN_DIM / 2) * GCN_H) {
        int r  = idx - RNN_H * 192;
        int k2 = r / GCN_H;
        int j  = r % GCN_H;
        g_Wgp[r] = make_float2(Wg[(2 * k2) * GCN_H + j], Wg[(2 * k2 + 1) * GCN_H + j]);
    }
}

__device__ __forceinline__ float sigf(float v) {
    return 1.0f / (1.0f + expf(-v));
}

// ---------------------------------------------------------------------------
// Fused per-env GCN + GRU. 1 env per block, 256 threads.
// ---------------------------------------------------------------------------
__global__ __launch_bounds__(256) void fused_gcn_gru(
    const float* __restrict__ x,          // [env,16,128]
    const int*   __restrict__ ei,         // [env,2,128]  (int32)
    const float* __restrict__ prev_h,     // [env,16,64]
    const float* __restrict__ bg,         // [64]
    const float* __restrict__ b_ih,       // [192]
    const float* __restrict__ b_hh,       // [192]
    float*       __restrict__ h_out)      // [env,16,64]  (h_new destination)
{
    __shared__ __align__(16) float  x_s[NUM_AGENTS * IN_DIM];   // 8 KB
    __shared__ __align__(16) float2 gh_s[NUM_AGENTS * RNN_H];   // 8 KB (.x=gcn_out, .y=prev_h)
    __shared__ float  xw_s[NUM_AGENTS * GCN_H];                 // 4 KB
    __shared__ float  agg_s[NUM_AGENTS * 65];                   // padded
    __shared__ int    row_s[E_PER_GRAPH], col_s[E_PER_GRAPH];
    __shared__ float  deg_s[NUM_AGENTS], dinv_s[NUM_AGENTS];

    const int env = blockIdx.x;
    const int t   = threadIdx.x;

    // ---- cooperative loads ----
    const float4* xe = (const float4*)(x + (size_t)env * (NUM_AGENTS * IN_DIM));
    #pragma unroll
    for (int i = 0; i < 2; i++)
        ((float4*)x_s)[t + i * 256] = xe[t + i * 256];

    const float* he = prev_h + (size_t)env * FLAT_H;
    #pragma unroll
    for (int i = 0; i < 4; i++)
        gh_s[t + i * 256].y = he[t + i * 256];

    const int* ee = ei + (size_t)env * (2 * E_PER_GRAPH);
    if (t < E_PER_GRAPH)      row_s[t] = ee[t];
    else                      col_s[t - E_PER_GRAPH] = ee[t];

    if (t < NUM_AGENTS) deg_s[t] = 1.0f;
    __syncthreads();

    // ---- degree ----
    if (t < E_PER_GRAPH) atomicAdd(&deg_s[col_s[t]], 1.0f);
    __syncthreads();
    if (t < NUM_AGENTS) dinv_s[t] = rsqrtf(deg_s[t]);

    const int j  = t & 63;
    const int rq = t >> 6;   // 0..3

    // ---- xw = x @ W_gcn  (4 rows per thread, FFMA2 over k-pairs) ----
    {
        ull a0 = 0ull, a1 = 0ull, a2 = 0ull, a3 = 0ull;   // bits(0,0) == (0.f,0.f)
        const ull* wgp = (const ull*)g_Wgp;
        const ull* xs2 = (const ull*)x_s;                  // row stride = 64 ulls
        #pragma unroll 8
        for (int k2 = 0; k2 < IN_DIM / 2; k2++) {
            ull w = wgp[k2 * GCN_H + j];
            ffma2(a0, xs2[(rq     ) * 64 + k2], w);
            ffma2(a1, xs2[(rq +  4) * 64 + k2], w);
            ffma2(a2, xs2[(rq +  8) * 64 + k2], w);
            ffma2(a3, xs2[(rq + 12) * 64 + k2], w);
        }
        float2 v0 = unpack2(a0), v1 = unpack2(a1), v2 = unpack2(a2), v3 = unpack2(a3);
        xw_s[(rq     ) * 64 + j] = v0.x + v0.y;
        xw_s[(rq +  4) * 64 + j] = v1.x + v1.y;
        xw_s[(rq +  8) * 64 + j] = v2.x + v2.y;
        xw_s[(rq + 12) * 64 + j] = v3.x + v3.y;
    }
    __syncthreads();

    // ---- self-loop init: agg = xw / deg ----
    #pragma unroll
    for (int i = 0; i < 4; i++) {
        int r = rq + 4 * i;
        agg_s[r * 65 + j] = xw_s[r * 64 + j] / deg_s[r];
    }
    __syncthreads();

    // ---- edge scatter: agg[col] += dinv[row]*dinv[col]*xw[row] ----
    #pragma unroll
    for (int i = 0; i < 32; i++) {
        int e  = rq + 4 * i;
        int rr = row_s[e];
        int cc = col_s[e];
        float v = dinv_s[rr] * dinv_s[cc] * xw_s[rr * 64 + j];
        atomicAdd(&agg_s[cc * 65 + j], v);
    }
    __syncthreads();

    // ---- gcn_out = agg + b_gcn → gh_s.x ----
    {
        float bgj = bg[j];
        #pragma unroll
        for (int i = 0; i < 4; i++) {
            int r = rq + 4 * i;
            gh_s[r * 64 + j].x = agg_s[r * 65 + j] + bgj;
        }
    }
    __syncthreads();

    // ---- GRU: 4 rows × 3 paired dots per thread (FFMA2, lanes = x/h parts) ----
    ull arbr[4] = {0,0,0,0}, azbz[4] = {0,0,0,0}, anbn[4] = {0,0,0,0};
    const ull* ghu = (const ull*)gh_s;
    const ull* wpk = (const ull*)g_Wpk;
    #pragma unroll 4
    for (int k = 0; k < RNN_H; k++) {
        const ull* wp = wpk + k * 192;
        ull wr = wp[j];
        ull wz = wp[64 + j];
        ull wn = wp[128 + j];
        #pragma unroll
        for (int i = 0; i < 4; i++) {
            ull gh = ghu[(rq + 4 * i) * 64 + k];
            ffma2(arbr[i], gh, wr);
            ffma2(azbz[i], gh, wz);
            ffma2(anbn[i], gh, wn);
        }
    }

    const float bihr = b_ih[j],       bhhr = b_hh[j];
    const float bihz = b_ih[64 + j],  bhhz = b_hh[64 + j];
    const float bihn = b_ih[128 + j], bhhn = b_hh[128 + j];

    float* hb = h_out + (size_t)env * FLAT_H;
    #pragma unroll
    for (int i = 0; i < 4; i++) {
        int r = rq + 4 * i;
        float2 vr = unpack2(arbr[i]);
        float2 vz = unpack2(azbz[i]);
        float2 vn = unpack2(anbn[i]);
        float rg = sigf(vr.x + vr.y + bihr + bhhr);
        float z  = sigf(vz.x + vz.y + bihz + bhhz);
        float n  = tanhf(vn.x + bihn + rg * (vn.y + bhhn));
        float h  = gh_s[r * 64 + j].y;
        hb[r * 64 + j] = (1.0f - z) * n + z * h;
    }
}

// ---------------------------------------------------------------------------
// logits = h_new [16384,1024] @ W_lin^T [1024,512] + b_lin
// BM=128, BN=128, BK=16, 256 threads, 8x8 microtile, FFMA2 paired along N.
// ---------------------------------------------------------------------------
#define BM 128
#define BN 128
#define BK 16

__global__ __launch_bounds__(256) void gemm512(
    const float* __restrict__ A,      // [16384,1024] h_new
    const float* __restrict__ Wl,     // [512,1024] row-major
    const float* __restrict__ bias,   // [512]
    float*       __restrict__ C)      // [16384,512]
{
    __shared__ __align__(16) float As[BK][BM + 4];   // stride 132
    __shared__ __align__(16) float Bs[BK][BN + 4];   // stride 132

    const int bm = blockIdx.y * BM;
    const int bn = blockIdx.x * BN;
    const int t  = threadIdx.x;
    const int tx = t & 15;     // 0..15 (N dir, x8)
    const int ty = t >> 4;     // 0..15 (M dir, x8)

    const int lrow = t >> 2;   // 0..63 base? no: see below
    const int lkv  = t & 3;

    ull acc[8][4];
    #pragma unroll
    for (int i = 0; i < 8; i++)
        #pragma unroll
        for (int jj = 0; jj < 4; jj++) acc[i][jj] = 0ull;

    // prefetch tile 0
    float4 pa[2], pb[2];
    #pragma unroll
    for (int i = 0; i < 2; i++) {
        int id  = t + i * 256;
        int row = id >> 2, kv = id & 3;
        pa[i] = *(const float4*)(A  + (size_t)(bm + row) * FLAT_H + kv * 4);
        pb[i] = *(const float4*)(Wl + (size_t)(bn + row) * FLAT_H + kv * 4);
    }

    for (int k0 = 0; k0 < FLAT_H; k0 += BK) {
        // store prefetched tile to smem
        #pragma unroll
        for (int i = 0; i < 2; i++) {
            int id  = t + i * 256;
            int row = id >> 2, kv = id & 3;
            As[kv * 4 + 0][row] = pa[i].x;
            As[kv * 4 + 1][row] = pa[i].y;
            As[kv * 4 + 2][row] = pa[i].z;
            As[kv * 4 + 3][row] = pa[i].w;
            Bs[kv * 4 + 0][row] = pb[i].x;
            Bs[kv * 4 + 1][row] = pb[i].y;
            Bs[kv * 4 + 2][row] = pb[i].z;
            Bs[kv * 4 + 3][row] = pb[i].w;
        }
        __syncthreads();

        // prefetch next tile
        if (k0 + BK < FLAT_H) {
            #pragma unroll
            for (int i = 0; i < 2; i++) {
                int id  = t + i * 256;
                int row = id >> 2, kv = id & 3;
                pa[i] = *(const float4*)(A  + (size_t)(bm + row) * FLAT_H + (k0 + BK) + kv * 4);
                pb[i] = *(const float4*)(Wl + (size_t)(bn + row) * FLAT_H + (k0 + BK) + kv * 4);
            }
        }

        #pragma unroll
        for (int kk = 0; kk < BK; kk++) {
            float4 A0 = *(const float4*)&As[kk][ty * 8];
            float4 A1 = *(const float4*)&As[kk][ty * 8 + 4];
            float4 B0 = *(const float4*)&Bs[kk][tx * 8];
            float4 B1 = *(const float4*)&Bs[kk][tx * 8 + 4];
            ull b2[4];
            b2[0] = pack2(B0.x, B0.y);
            b2[1] = pack2(B0.z, B0.w);
            b2[2] = pack2(B1.x, B1.y);
            b2[3] = pack2(B1.z, B1.w);
            float a[8] = {A0.x, A0.y, A0.z, A0.w, A1.x, A1.y, A1.z, A1.w};
            #pragma unroll
            for (int i = 0; i < 8; i++) {
                ull a2 = bcast2(a[i]);
                ffma2(acc[i][0], a2, b2[0]);
                ffma2(acc[i][1], a2, b2[1]);
                ffma2(acc[i][2], a2, b2[2]);
                ffma2(acc[i][3], a2, b2[3]);
            }
        }
        __syncthreads();
    }

    // epilogue: fused bias, float4 stores (pairs are contiguous along N)
    float4 bv0 = *(const float4*)(bias + bn + tx * 8);
    float4 bv1 = *(const float4*)(bias + bn + tx * 8 + 4);
    #pragma unroll
    for (int i = 0; i < 8; i++) {
        int row = bm + ty * 8 + i;
        float2 c0 = unpack2(acc[i][0]);
        float2 c1 = unpack2(acc[i][1]);
        float2 c2 = unpack2(acc[i][2]);
        float2 c3 = unpack2(acc[i][3]);
        float4 o0 = make_float4(c0.x + bv0.x, c0.y + bv0.y, c1.x + bv0.z, c1.y + bv0.w);
        float4 o1 = make_float4(c2.x + bv1.x, c2.y + bv1.y, c3.x + bv1.z, c3.y + bv1.w);
        *(float4*)(C + (size_t)row * OUT_DIM + bn + tx * 8)     = o0;
        *(float4*)(C + (size_t)row * OUT_DIM + bn + tx * 8 + 4) = o1;
    }
}

// ---------------------------------------------------------------------------
extern "C" void kernel_launch(void* const* d_in, const int* in_sizes, int n_in,
                              void* d_out, int out_size) {
    const float* x     = (const float*)d_in[0];
    const int*   ei    = (const int*)  d_in[1];   // jax default: int64 -> int32
    const float* ph    = (const float*)d_in[2];
    const float* Wg    = (const float*)d_in[3];
    const float* bg    = (const float*)d_in[4];
    const float* W_ih  = (const float*)d_in[5];
    const float* W_hh  = (const float*)d_in[6];
    const float* b_ih  = (const float*)d_in[7];
    const float* b_hh  = (const float*)d_in[8];
    const float* W_lin = (const float*)d_in[9];
    const float* b_lin = (const float*)d_in[10];

    float* out = (float*)d_out;
    // tuple output: [logits (16384*512) | next_h (16384*1024)]
    bool has_nh = (out_size >= NUM_ENVS * (OUT_DIM + FLAT_H));
    float* hdst;
    if (has_nh) {
        hdst = out + (size_t)NUM_ENVS * OUT_DIM;     // write h_new directly to output
    } else {
        cudaGetSymbolAddress((void**)&hdst, g_hbuf); // fallback scratch
    }

    pack_w_kernel<<<64, 256>>>(W_ih, W_hh, Wg);
    fused_gcn_gru<<<NUM_ENVS, 256>>>(x, ei, ph, bg, b_ih, b_hh, hdst);
    gemm512<<<dim3(OUT_DIM / BN, NUM_ENVS / BM), 256>>>(hdst, W_lin, b_lin, out);
}

// round 6
// speedup vs baseline: 1.2249x; 1.2249x over previous
#include <cuda_runtime.h>
#include <cuda_bf16.h>
#include <math.h>
#include <cstdint>

#define NUM_ENVS 16384
#define NUM_AGENTS 16
#define IN_DIM 128
#define GCN_H 64
#define RNN_H 64
#define E_PER_GRAPH 128
#define OUT_DIM 512                   // 16*4*8
#define FLAT_H (NUM_AGENTS * RNN_H)   // 1024

typedef unsigned long long ull;

// ---------------- static device scratch (no allocation allowed) -------------
__device__ float  g_hbuf[(size_t)NUM_ENVS * FLAT_H];            // fallback h_new
__device__ float2 g_Wpk[RNN_H * 3 * RNN_H];                     // GRU packed weights
__device__ float2 g_Wgp[(IN_DIM / 2) * GCN_H];                  // GCN packed weights
__device__ __align__(16) __nv_bfloat16 g_Ah[(size_t)NUM_ENVS * FLAT_H];  // h_new hi
__device__ __align__(16) __nv_bfloat16 g_Al[(size_t)NUM_ENVS * FLAT_H];  // h_new lo
__device__ __align__(16) __nv_bfloat16 g_Bh[(size_t)OUT_DIM * FLAT_H];   // W_lin hi
__device__ __align__(16) __nv_bfloat16 g_Bl[(size_t)OUT_DIM * FLAT_H];   // W_lin lo

// ---------------- helpers ---------------------------------------------------
__device__ __forceinline__ uint32_t smem_to_u32(const void* p) {
    uint32_t a;
    asm("{ .reg .u64 t; cvta.to.shared.u64 t, %1; cvt.u32.u64 %0, t; }" : "=r"(a) : "l"(p));
    return a;
}
__device__ __forceinline__ void ffma2(ull& d, ull a, ull b) {
    asm("fma.rn.f32x2 %0, %1, %2, %0;" : "+l"(d) : "l"(a), "l"(b));
}
__device__ __forceinline__ float2 unpack2(ull u) {
    float2 f; asm("mov.b64 {%0, %1}, %2;" : "=f"(f.x), "=f"(f.y) : "l"(u)); return f;
}
__device__ __forceinline__ float sigf(float v) { return 1.0f / (1.0f + expf(-v)); }

__device__ __forceinline__ void ldmx4(uint32_t* r, uint32_t addr) {
    asm volatile("ldmatrix.sync.aligned.m8n8.x4.shared.b16 {%0,%1,%2,%3}, [%4];"
                 : "=r"(r[0]), "=r"(r[1]), "=r"(r[2]), "=r"(r[3]) : "r"(addr));
}
__device__ __forceinline__ void mma16816(float* d, const uint32_t* a, const uint32_t* b) {
    asm volatile("mma.sync.aligned.m16n8k16.row.col.f32.bf16.bf16.f32 "
                 "{%0,%1,%2,%3}, {%4,%5,%6,%7}, {%8,%9}, {%0,%1,%2,%3};"
                 : "+f"(d[0]), "+f"(d[1]), "+f"(d[2]), "+f"(d[3])
                 : "r"(a[0]), "r"(a[1]), "r"(a[2]), "r"(a[3]), "r"(b[0]), "r"(b[1]));
}

// ---------------------------------------------------------------------------
// pack weights: GRU pairs, GCN k-pairs, W_lin hi/lo bf16 split
// ---------------------------------------------------------------------------
#define PACK_N0 (RNN_H * 192)
#define PACK_N1 ((IN_DIM / 2) * GCN_H)
#define PACK_N2 (OUT_DIM * FLAT_H)
#define PACK_TOT (PACK_N0 + PACK_N1 + PACK_N2)

__global__ void pack_w_kernel(const float* __restrict__ W_ih,
                              const float* __restrict__ W_hh,
                              const float* __restrict__ Wg,
                              const float* __restrict__ Wl) {
    int idx = blockIdx.x * 256 + threadIdx.x;
    if (idx < PACK_N0) {
        int k = idx / 192, g = idx % 192;
        g_Wpk[idx] = make_float2(W_ih[g * RNN_H + k], W_hh[g * RNN_H + k]);
    } else if (idx < PACK_N0 + PACK_N1) {
        int r = idx - PACK_N0;
        int k2 = r / GCN_H, j = r % GCN_H;
        g_Wgp[r] = make_float2(Wg[(2 * k2) * GCN_H + j], Wg[(2 * k2 + 1) * GCN_H + j]);
    } else if (idx < PACK_TOT) {
        int r = idx - PACK_N0 - PACK_N1;
        float w = Wl[r];
        __nv_bfloat16 hi = __float2bfloat16(w);
        g_Bh[r] = hi;
        g_Bl[r] = __float2bfloat16(w - __bfloat162float(hi));
    }
}

// ---------------------------------------------------------------------------
// Fused per-env GCN + GRU. 1 env per block, 256 threads.
// Epilogue emits h_new (fp32) plus hi/lo bf16 split for the tensor GEMM.
// ---------------------------------------------------------------------------
__global__ __launch_bounds__(256) void fused_gcn_gru(
    const float* __restrict__ x, const int* __restrict__ ei,
    const float* __restrict__ prev_h, const float* __restrict__ bg,
    const float* __restrict__ b_ih, const float* __restrict__ b_hh,
    float* __restrict__ h_out)
{
    __shared__ __align__(16) float  x_s[NUM_AGENTS * IN_DIM];
    __shared__ __align__(16) float2 gh_s[NUM_AGENTS * RNN_H];
    __shared__ float  xw_s[NUM_AGENTS * GCN_H];
    __shared__ float  agg_s[NUM_AGENTS * 65];
    __shared__ int    row_s[E_PER_GRAPH], col_s[E_PER_GRAPH];
    __shared__ float  deg_s[NUM_AGENTS], dinv_s[NUM_AGENTS];

    const int env = blockIdx.x;
    const int t   = threadIdx.x;

    const float4* xe = (const float4*)(x + (size_t)env * (NUM_AGENTS * IN_DIM));
    #pragma unroll
    for (int i = 0; i < 2; i++)
        ((float4*)x_s)[t + i * 256] = xe[t + i * 256];

    const float* he = prev_h + (size_t)env * FLAT_H;
    #pragma unroll
    for (int i = 0; i < 4; i++)
        gh_s[t + i * 256].y = he[t + i * 256];

    const int* ee = ei + (size_t)env * (2 * E_PER_GRAPH);
    if (t < E_PER_GRAPH)      row_s[t] = ee[t];
    else                      col_s[t - E_PER_GRAPH] = ee[t];

    if (t < NUM_AGENTS) deg_s[t] = 1.0f;
    __syncthreads();

    if (t < E_PER_GRAPH) atomicAdd(&deg_s[col_s[t]], 1.0f);
    __syncthreads();
    if (t < NUM_AGENTS) dinv_s[t] = rsqrtf(deg_s[t]);

    const int j  = t & 63;
    const int rq = t >> 6;

    {   // xw = x @ W_gcn (FFMA2 over k-pairs)
        ull a0 = 0ull, a1 = 0ull, a2 = 0ull, a3 = 0ull;
        const ull* wgp = (const ull*)g_Wgp;
        const ull* xs2 = (const ull*)x_s;
        #pragma unroll 8
        for (int k2 = 0; k2 < IN_DIM / 2; k2++) {
            ull w = wgp[k2 * GCN_H + j];
            ffma2(a0, xs2[(rq     ) * 64 + k2], w);
            ffma2(a1, xs2[(rq +  4) * 64 + k2], w);
            ffma2(a2, xs2[(rq +  8) * 64 + k2], w);
            ffma2(a3, xs2[(rq + 12) * 64 + k2], w);
        }
        float2 v0 = unpack2(a0), v1 = unpack2(a1), v2 = unpack2(a2), v3 = unpack2(a3);
        xw_s[(rq     ) * 64 + j] = v0.x + v0.y;
        xw_s[(rq +  4) * 64 + j] = v1.x + v1.y;
        xw_s[(rq +  8) * 64 + j] = v2.x + v2.y;
        xw_s[(rq + 12) * 64 + j] = v3.x + v3.y;
    }
    __syncthreads();

    #pragma unroll
    for (int i = 0; i < 4; i++) {
        int r = rq + 4 * i;
        agg_s[r * 65 + j] = xw_s[r * 64 + j] / deg_s[r];
    }
    __syncthreads();

    #pragma unroll
    for (int i = 0; i < 32; i++) {
        int e  = rq + 4 * i;
        int rr = row_s[e];
        int cc = col_s[e];
        atomicAdd(&agg_s[cc * 65 + j], dinv_s[rr] * dinv_s[cc] * xw_s[rr * 64 + j]);
    }
    __syncthreads();

    {
        float bgj = bg[j];
        #pragma unroll
        for (int i = 0; i < 4; i++) {
            int r = rq + 4 * i;
            gh_s[r * 64 + j].x = agg_s[r * 65 + j] + bgj;
        }
    }
    __syncthreads();

    ull arbr[4] = {0,0,0,0}, azbz[4] = {0,0,0,0}, anbn[4] = {0,0,0,0};
    const ull* ghu = (const ull*)gh_s;
    const ull* wpk = (const ull*)g_Wpk;
    #pragma unroll 4
    for (int k = 0; k < RNN_H; k++) {
        const ull* wp = wpk + k * 192;
        ull wr = wp[j], wz = wp[64 + j], wn = wp[128 + j];
        #pragma unroll
        for (int i = 0; i < 4; i++) {
            ull gh = ghu[(rq + 4 * i) * 64 + k];
            ffma2(arbr[i], gh, wr);
            ffma2(azbz[i], gh, wz);
            ffma2(anbn[i], gh, wn);
        }
    }

    const float bihr = b_ih[j],       bhhr = b_hh[j];
    const float bihz = b_ih[64 + j],  bhhz = b_hh[64 + j];
    const float bihn = b_ih[128 + j], bhhn = b_hh[128 + j];

    float* hb = h_out + (size_t)env * FLAT_H;
    __nv_bfloat16* ah = g_Ah + (size_t)env * FLAT_H;
    __nv_bfloat16* al = g_Al + (size_t)env * FLAT_H;
    #pragma unroll
    for (int i = 0; i < 4; i++) {
        int r = rq + 4 * i;
        float2 vr = unpack2(arbr[i]);
        float2 vz = unpack2(azbz[i]);
        float2 vn = unpack2(anbn[i]);
        float rg = sigf(vr.x + vr.y + bihr + bhhr);
        float z  = sigf(vz.x + vz.y + bihz + bhhz);
        float n  = tanhf(vn.x + bihn + rg * (vn.y + bhhn));
        float h  = gh_s[r * 64 + j].y;
        float hn = (1.0f - z) * n + z * h;
        hb[r * 64 + j] = hn;
        __nv_bfloat16 hhi = __float2bfloat16(hn);
        ah[r * 64 + j] = hhi;
        al[r * 64 + j] = __float2bfloat16(hn - __bfloat162float(hhi));
    }
}

// ---------------------------------------------------------------------------
// Tensor-core GEMM via mma.sync (HMMA, valid on baseline compute_103):
// logits = h_new @ W_lin^T + b_lin, bf16x3 split, fp32 accum.
// BM=128, BN=128, BK=32. 8 warps (2 M x 4 N), warp tile 64x32.
// smem tiles padded to stride 40 bf16 (80 B) -> conflict-free ldmatrix.
// ---------------------------------------------------------------------------
#define BK 32
#define TSTRIDE 40                       // bf16 elements per smem row
#define NCHUNK (FLAT_H / BK)             // 32

__global__ __launch_bounds__(256) void gemm_mma(
    const float* __restrict__ bias,   // [512]
    float*       __restrict__ C)      // [16384,512]
{
    __shared__ __align__(16) __nv_bfloat16 sAh[128 * TSTRIDE];
    __shared__ __align__(16) __nv_bfloat16 sAl[128 * TSTRIDE];
    __shared__ __align__(16) __nv_bfloat16 sBh[128 * TSTRIDE];
    __shared__ __align__(16) __nv_bfloat16 sBl[128 * TSTRIDE];

    const int t    = threadIdx.x;
    const int wid  = t >> 5;
    const int lane = t & 31;
    const int bn   = blockIdx.x * 128;
    const int bm   = blockIdx.y * 128;
    const int wm   = (wid >> 2) * 64;    // warp M offset (0 or 64)
    const int wn   = (wid & 3) * 32;     // warp N offset (0,32,64,96)

    const uint32_t ah_base = smem_to_u32(sAh);
    const uint32_t al_base = smem_to_u32(sAl);
    const uint32_t bh_base = smem_to_u32(sBh);
    const uint32_t bl_base = smem_to_u32(sBl);

    // ldmatrix address offsets for this lane
    // A x4: m = (lane&7) + ((lane>>3)&1)*8 ; k = ((lane>>4)&1)*8
    const int a_m = (lane & 7) + ((lane >> 3) & 1) * 8;
    const int a_k = ((lane >> 4) & 1) * 8;
    // B x4: n = (lane&7) + ((lane>>4)&1)*8 ; k = ((lane>>3)&1)*8
    const int b_n = (lane & 7) + ((lane >> 4) & 1) * 8;
    const int b_k = ((lane >> 3) & 1) * 8;

    float acc[4][4][4];
    #pragma unroll
    for (int mt = 0; mt < 4; mt++)
        #pragma unroll
        for (int ns = 0; ns < 4; ns++)
            #pragma unroll
            for (int q = 0; q < 4; q++) acc[mt][ns][q] = 0.0f;

    const uint4* gAh = (const uint4*)g_Ah;   // row stride = 128 uint4
    const uint4* gAl = (const uint4*)g_Al;
    const uint4* gBh = (const uint4*)g_Bh;
    const uint4* gBl = (const uint4*)g_Bl;

    for (int c = 0; c < NCHUNK; c++) {
        // ---- load tiles: each tile 128 rows x 4 uint4, 512 uint4 -> 2/thread
        #pragma unroll
        for (int i = 0; i < 2; i++) {
            int idx = t + i * 256;         // 0..511
            int row = idx >> 2;            // 0..127
            int q   = idx & 3;             // uint4 within 32-k row
            size_t ga = (size_t)(bm + row) * 128 + c * 4 + q;
            size_t gb = (size_t)(bn + row) * 128 + c * 4 + q;
            int so = row * TSTRIDE + q * 8;            // bf16 elems
            ((uint4*)(sAh + so))[0] = gAh[ga];
            ((uint4*)(sAl + so))[0] = gAl[ga];
            ((uint4*)(sBh + so))[0] = gBh[gb];
            ((uint4*)(sBl + so))[0] = gBl[gb];
        }
        __syncthreads();

        #pragma unroll
        for (int kk = 0; kk < 2; kk++) {   // two k16 steps per BK=32 chunk
            const int akcol = kk * 16 + a_k;
            const int bkcol = kk * 16 + b_k;

            uint32_t fAh[4][4], fAl[4][4];
            #pragma unroll
            for (int mt = 0; mt < 4; mt++) {
                uint32_t off = (uint32_t)(((wm + mt * 16 + a_m) * TSTRIDE + akcol) * 2);
                ldmx4(fAh[mt], ah_base + off);
                ldmx4(fAl[mt], al_base + off);
            }
            uint32_t fBh[2][4], fBl[2][4];
            #pragma unroll
            for (int nt = 0; nt < 2; nt++) {
                uint32_t off = (uint32_t)(((wn + nt * 16 + b_n) * TSTRIDE + bkcol) * 2);
                ldmx4(fBh[nt], bh_base + off);
                ldmx4(fBl[nt], bl_base + off);
            }

            #pragma unroll
            for (int mt = 0; mt < 4; mt++) {
                #pragma unroll
                for (int ns = 0; ns < 4; ns++) {
                    const uint32_t* bh = &fBh[ns >> 1][(ns & 1) * 2];
                    const uint32_t* bl = &fBl[ns >> 1][(ns & 1) * 2];
                    mma16816(acc[mt][ns], fAh[mt], bh);   // hi*hi
                    mma16816(acc[mt][ns], fAh[mt], bl);   // hi*lo
                    mma16816(acc[mt][ns], fAl[mt], bh);   // lo*hi
                }
            }
        }
        __syncthreads();
    }

    // ---- epilogue: fragment rows lane/4 (+8), cols (lane%4)*2 (+1)
    const int fr = lane >> 2;
    const int fc = (lane & 3) * 2;
    #pragma unroll
    for (int mt = 0; mt < 4; mt++) {
        #pragma unroll
        for (int ns = 0; ns < 4; ns++) {
            int col = bn + wn + ns * 8 + fc;
            float2 bv = *(const float2*)(bias + col);
            int r0 = bm + wm + mt * 16 + fr;
            float2 o0 = make_float2(acc[mt][ns][0] + bv.x, acc[mt][ns][1] + bv.y);
            float2 o1 = make_float2(acc[mt][ns][2] + bv.x, acc[mt][ns][3] + bv.y);
            *(float2*)(C + (size_t)r0 * OUT_DIM + col)       = o0;
            *(float2*)(C + (size_t)(r0 + 8) * OUT_DIM + col) = o1;
        }
    }
}

// ---------------------------------------------------------------------------
extern "C" void kernel_launch(void* const* d_in, const int* in_sizes, int n_in,
                              void* d_out, int out_size) {
    const float* x     = (const float*)d_in[0];
    const int*   ei    = (const int*)  d_in[1];
    const float* ph    = (const float*)d_in[2];
    const float* Wg    = (const float*)d_in[3];
    const float* bg    = (const float*)d_in[4];
    const float* W_ih  = (const float*)d_in[5];
    const float* W_hh  = (const float*)d_in[6];
    const float* b_ih  = (const float*)d_in[7];
    const float* b_hh  = (const float*)d_in[8];
    const float* W_lin = (const float*)d_in[9];
    const float* b_lin = (const float*)d_in[10];

    float* out = (float*)d_out;
    bool has_nh = (out_size >= NUM_ENVS * (OUT_DIM + FLAT_H));
    float* hdst;
    if (has_nh) {
        hdst = out + (size_t)NUM_ENVS * OUT_DIM;
    } else {
        cudaGetSymbolAddress((void**)&hdst, g_hbuf);
    }

    pack_w_kernel<<<(PACK_TOT + 255) / 256, 256>>>(W_ih, W_hh, Wg, W_lin);
    fused_gcn_gru<<<NUM_ENVS, 256>>>(x, ei, ph, bg, b_ih, b_hh, hdst);
    gemm_mma<<<dim3(OUT_DIM / 128, NUM_ENVS / 128), 256>>>(b_lin, out);
}

// round 7
// speedup vs baseline: 2.0773x; 1.6958x over previous
#include <cuda_runtime.h>
#include <cuda_bf16.h>
#include <math.h>
#include <cstdint>

#define NUM_ENVS 16384
#define NUM_AGENTS 16
#define IN_DIM 128
#define GCN_H 64
#define RNN_H 64
#define E_PER_GRAPH 128
#define OUT_DIM 512
#define FLAT_H (NUM_AGENTS * RNN_H)      // 1024
#define NNODE ((size_t)NUM_ENVS * NUM_AGENTS)   // 262144

// ---------------- static device scratch -------------------------------------
__device__ float  g_hbuf[(size_t)NUM_ENVS * FLAT_H];
__device__ float  g_xw[NNODE * GCN_H];                           // GEMM1 out
__device__ __align__(16) __nv_bfloat16 g_A2h[NNODE * 128];       // [gcn|h] hi
__device__ __align__(16) __nv_bfloat16 g_A2l[NNODE * 128];       // [gcn|h] lo
__device__ __align__(16) __nv_bfloat16 g_Ah[NNODE * RNN_H];      // h_new hi
__device__ __align__(16) __nv_bfloat16 g_Al[NNODE * RNN_H];      // h_new lo
__device__ __align__(16) __nv_bfloat16 g_Wgth[GCN_H * IN_DIM];   // Wgcn^T hi
__device__ __align__(16) __nv_bfloat16 g_Wgtl[GCN_H * IN_DIM];   // Wgcn^T lo
__device__ __align__(16) __nv_bfloat16 g_B2h[256 * 128];         // gates B hi
__device__ __align__(16) __nv_bfloat16 g_B2l[256 * 128];         // gates B lo
__device__ float g_b2[256];                                      // gate biases
__device__ __align__(16) __nv_bfloat16 g_Bh[(size_t)OUT_DIM * FLAT_H];
__device__ __align__(16) __nv_bfloat16 g_Bl[(size_t)OUT_DIM * FLAT_H];

// ---------------- helpers ---------------------------------------------------
__device__ __forceinline__ uint32_t smem_to_u32(const void* p) {
    uint32_t a;
    asm("{ .reg .u64 t; cvta.to.shared.u64 t, %1; cvt.u32.u64 %0, t; }" : "=r"(a) : "l"(p));
    return a;
}
__device__ __forceinline__ float sigf(float v) { return 1.0f / (1.0f + expf(-v)); }

__device__ __forceinline__ void ldmx4(uint32_t* r, uint32_t addr) {
    asm volatile("ldmatrix.sync.aligned.m8n8.x4.shared.b16 {%0,%1,%2,%3}, [%4];"
                 : "=r"(r[0]), "=r"(r[1]), "=r"(r[2]), "=r"(r[3]) : "r"(addr));
}
__device__ __forceinline__ void mma16816(float* d, const uint32_t* a, const uint32_t* b) {
    asm volatile("mma.sync.aligned.m16n8k16.row.col.f32.bf16.bf16.f32 "
                 "{%0,%1,%2,%3}, {%4,%5,%6,%7}, {%8,%9}, {%0,%1,%2,%3};"
                 : "+f"(d[0]), "+f"(d[1]), "+f"(d[2]), "+f"(d[3])
                 : "r"(a[0]), "r"(a[1]), "r"(a[2]), "r"(a[3]), "r"(b[0]), "r"(b[1]));
}
__device__ __forceinline__ void split_bf16(float f, __nv_bfloat16& hi, __nv_bfloat16& lo) {
    hi = __float2bfloat16(f);
    lo = __float2bfloat16(f - __bfloat162float(hi));
}

// ---------------------------------------------------------------------------
// pack: Wgcn^T hi/lo, gate matrix B2 (interleaved cols 4j+{r,z,nx,nh}), b2,
// W_lin hi/lo.
// ---------------------------------------------------------------------------
#define PK_WGT (GCN_H * IN_DIM)                  // 8192
#define PK_B2  (256 * 128)                       // 32768
#define PK_WL  (OUT_DIM * FLAT_H)                // 524288
#define PK_TOT (PK_WGT + PK_B2 + 256 + PK_WL)

__global__ void pack_w_kernel(const float* __restrict__ Wg,
                              const float* __restrict__ W_ih,
                              const float* __restrict__ W_hh,
                              const float* __restrict__ b_ih,
                              const float* __restrict__ b_hh,
                              const float* __restrict__ Wl) {
    int idx = blockIdx.x * 256 + threadIdx.x;
    if (idx < PK_WGT) {
        int n = idx >> 7, k = idx & 127;                 // Wgt[n][k] = Wg[k][n]
        split_bf16(Wg[k * GCN_H + n], g_Wgth[idx], g_Wgtl[idx]);
    } else if (idx < PK_WGT + PK_B2) {
        int r = idx - PK_WGT;
        int n = r >> 7, k = r & 127;
        int j = n >> 2, g = n & 3;
        float w = 0.0f;
        if (g == 0)      w = (k < 64) ? W_ih[j * 64 + k]         : W_hh[j * 64 + (k - 64)];
        else if (g == 1) w = (k < 64) ? W_ih[(64 + j) * 64 + k]  : W_hh[(64 + j) * 64 + (k - 64)];
        else if (g == 2) w = (k < 64) ? W_ih[(128 + j) * 64 + k] : 0.0f;
        else             w = (k < 64) ? 0.0f                     : W_hh[(128 + j) * 64 + (k - 64)];
        split_bf16(w, g_B2h[r], g_B2l[r]);
    } else if (idx < PK_WGT + PK_B2 + 256) {
        int n = idx - PK_WGT - PK_B2;
        int j = n >> 2, g = n & 3;
        float b;
        if (g == 0)      b = b_ih[j] + b_hh[j];
        else if (g == 1) b = b_ih[64 + j] + b_hh[64 + j];
        else if (g == 2) b = b_ih[128 + j];
        else             b = b_hh[128 + j];
        g_b2[n] = b;
    } else if (idx < PK_TOT) {
        int r = idx - PK_WGT - PK_B2 - 256;
        split_bf16(Wl[r], g_Bh[r], g_Bl[r]);
    }
}

// ---------------------------------------------------------------------------
// GEMM1: xw[262144,64] = x[262144,128] @ Wgcn[128,64]   (bf16x3, fp32 acc)
// BM=128, N=64, BK=32. 256 thr, 8 warps (4M x 2N), warp tile 32x32.
// A converted fp32->hi/lo during tile load.
// ---------------------------------------------------------------------------
#define TS 40      // smem tile k-stride in bf16

__global__ __launch_bounds__(256) void gemm_xw(const float* __restrict__ x) {
    __shared__ __align__(16) __nv_bfloat16 sAh[128 * TS];
    __shared__ __align__(16) __nv_bfloat16 sAl[128 * TS];
    __shared__ __align__(16) __nv_bfloat16 sBh[64 * TS];
    __shared__ __align__(16) __nv_bfloat16 sBl[64 * TS];

    const int t = threadIdx.x, wid = t >> 5, lane = t & 31;
    const size_t bm = (size_t)blockIdx.x * 128;
    const int wm = (wid >> 1) * 32, wn = (wid & 1) * 32;
    const uint32_t ah = smem_to_u32(sAh), al = smem_to_u32(sAl);
    const uint32_t bh = smem_to_u32(sBh), bl = smem_to_u32(sBl);

    const int a_m = (lane & 7) + ((lane >> 3) & 1) * 8;
    const int a_k = ((lane >> 4) & 1) * 8;
    const int b_n = (lane & 7) + ((lane >> 4) & 1) * 8;
    const int b_k = ((lane >> 3) & 1) * 8;

    float acc[2][4][4];
    #pragma unroll
    for (int mt = 0; mt < 2; mt++)
        #pragma unroll
        for (int nt = 0; nt < 4; nt++)
            #pragma unroll
            for (int q = 0; q < 4; q++) acc[mt][nt][q] = 0.0f;

    for (int c = 0; c < 4; c++) {
        // A: 128 rows x 32 k fp32 -> hi/lo
        #pragma unroll
        for (int i = 0; i < 4; i++) {
            int idx = t + i * 256;            // 0..1023 float4 slots
            int row = idx >> 3, q = idx & 7;  // q: float4 within 32 floats
            float4 v = *(const float4*)(x + (bm + row) * IN_DIM + c * 32 + q * 4);
            __nv_bfloat16 h0, l0, h1, l1, h2, l2, h3, l3;
            split_bf16(v.x, h0, l0); split_bf16(v.y, h1, l1);
            split_bf16(v.z, h2, l2); split_bf16(v.w, h3, l3);
            __nv_bfloat162* ph = (__nv_bfloat162*)(sAh + row * TS + q * 4);
            __nv_bfloat162* pl = (__nv_bfloat162*)(sAl + row * TS + q * 4);
            ph[0] = __nv_bfloat162(h0, h1); ph[1] = __nv_bfloat162(h2, h3);
            pl[0] = __nv_bfloat162(l0, l1); pl[1] = __nv_bfloat162(l2, l3);
        }
        // B: 64 rows x 32 k bf16 hi/lo (256 uint4 -> 1/thread)
        {
            int row = t >> 2, q = t & 3;
            ((uint4*)(sBh + row * TS + q * 8))[0] = ((const uint4*)g_Wgth)[row * 16 + c * 4 + q];
            ((uint4*)(sBl + row * TS + q * 8))[0] = ((const uint4*)g_Wgtl)[row * 16 + c * 4 + q];
        }
        __syncthreads();

        #pragma unroll
        for (int kk = 0; kk < 2; kk++) {
            uint32_t fAh[2][4], fAl[2][4];
            #pragma unroll
            for (int mt = 0; mt < 2; mt++) {
                uint32_t off = (uint32_t)(((wm + mt * 16 + a_m) * TS + kk * 16 + a_k) * 2);
                ldmx4(fAh[mt], ah + off);
                ldmx4(fAl[mt], al + off);
            }
            #pragma unroll
            for (int ntg = 0; ntg < 2; ntg++) {
                uint32_t fBh[4], fBl[4];
                uint32_t off = (uint32_t)(((wn + ntg * 16 + b_n) * TS + kk * 16 + b_k) * 2);
                ldmx4(fBh, bh + off);
                ldmx4(fBl, bl + off);
                #pragma unroll
                for (int mt = 0; mt < 2; mt++)
                    #pragma unroll
                    for (int p = 0; p < 2; p++) {
                        float* a = acc[mt][ntg * 2 + p];
                        mma16816(a, fAh[mt], &fBh[p * 2]);
                        mma16816(a, fAh[mt], &fBl[p * 2]);
                        mma16816(a, fAl[mt], &fBh[p * 2]);
                    }
            }
        }
        __syncthreads();
    }

    const int fr = lane >> 2, fc = (lane & 3) * 2;
    #pragma unroll
    for (int mt = 0; mt < 2; mt++)
        #pragma unroll
        for (int nt = 0; nt < 4; nt++) {
            int n = wn + nt * 8 + fc;
            size_t r0 = bm + wm + mt * 16 + fr;
            *(float2*)(g_xw + r0 * GCN_H + n)       = make_float2(acc[mt][nt][0], acc[mt][nt][1]);
            *(float2*)(g_xw + (r0 + 8) * GCN_H + n) = make_float2(acc[mt][nt][2], acc[mt][nt][3]);
        }
}

// ---------------------------------------------------------------------------
// Scatter: per-env adjacency build + agg = Adj @ xw; writes A2 = [gcn|h] hi/lo.
// 1 env per 128-thread block.
// ---------------------------------------------------------------------------
__global__ __launch_bounds__(128) void scatter_kernel(
    const int* __restrict__ ei, const float* __restrict__ prev_h,
    const float* __restrict__ bg)
{
    __shared__ __align__(16) float xw_s[NUM_AGENTS * GCN_H];
    __shared__ float Adj[NUM_AGENTS * NUM_AGENTS];
    __shared__ float deg_s[NUM_AGENTS], dinv_s[NUM_AGENTS];

    const int env = blockIdx.x;
    const int t   = threadIdx.x;

    if (t < NUM_AGENTS) deg_s[t] = 1.0f;
    #pragma unroll
    for (int i = 0; i < 2; i++) Adj[t + i * 128] = 0.0f;

    // xw tile load
    #pragma unroll
    for (int i = 0; i < 2; i++)
        ((float4*)xw_s)[t + i * 128] =
            ((const float4*)(g_xw + (size_t)env * NUM_AGENTS * GCN_H))[t + i * 128];

    const int rr = ei[(size_t)env * 256 + t];
    const int cc = ei[(size_t)env * 256 + 128 + t];
    __syncthreads();

    atomicAdd(&deg_s[cc], 1.0f);
    __syncthreads();
    if (t < NUM_AGENTS) dinv_s[t] = rsqrtf(deg_s[t]);
    __syncthreads();

    atomicAdd(&Adj[cc * 16 + rr], dinv_s[rr] * dinv_s[cc]);
    if (t < NUM_AGENTS) atomicAdd(&Adj[t * 16 + t], dinv_s[t] * dinv_s[t]);
    __syncthreads();

    // agg = Adj @ xw, then + bias, split, store to A2 cols [0,64)
    const int j  = t & 63;
    const int cq = t >> 6;   // 0..1
    float xv[NUM_AGENTS];
    #pragma unroll
    for (int r = 0; r < NUM_AGENTS; r++) xv[r] = xw_s[r * GCN_H + j];
    const float bgj = bg[j];

    #pragma unroll
    for (int i = 0; i < 8; i++) {
        int c = cq * 8 + i;
        float s = 0.0f;
        #pragma unroll
        for (int r = 0; r < NUM_AGENTS; r++) s += Adj[c * 16 + r] * xv[r];
        s += bgj;
        size_t node = (size_t)env * NUM_AGENTS + c;
        __nv_bfloat16 hi, lo;
        split_bf16(s, hi, lo);
        g_A2h[node * 128 + j] = hi;
        g_A2l[node * 128 + j] = lo;
    }

    // prev_h -> A2 cols [64,128)
    #pragma unroll
    for (int i = 0; i < 2; i++) {
        int f4 = t + i * 128;                     // 0..255
        float4 v = ((const float4*)(prev_h + (size_t)env * FLAT_H))[f4];
        int row = f4 >> 4, jj = (f4 & 15) * 4;
        size_t node = (size_t)env * NUM_AGENTS + row;
        __nv_bfloat16 h0, l0, h1, l1, h2, l2, h3, l3;
        split_bf16(v.x, h0, l0); split_bf16(v.y, h1, l1);
        split_bf16(v.z, h2, l2); split_bf16(v.w, h3, l3);
        __nv_bfloat162* ph = (__nv_bfloat162*)(g_A2h + node * 128 + 64 + jj);
        __nv_bfloat162* pl = (__nv_bfloat162*)(g_A2l + node * 128 + 64 + jj);
        ph[0] = __nv_bfloat162(h0, h1); ph[1] = __nv_bfloat162(h2, h3);
        pl[0] = __nv_bfloat162(l0, l1); pl[1] = __nv_bfloat162(l2, l3);
    }
}

// ---------------------------------------------------------------------------
// GEMM2: gates = A2[262144,128] @ B2^T[256,128] (bf16x3) + fused GRU epilogue.
// BM=128, BN=256 (full), BK=32. 512 thr, 16 warps (4M x 4N), warp tile 32x64.
// Gate layout: col 4j+{0:r_sum,1:z_sum,2:nx,3:nh}. shfl_xor(1) pairs lanes.
// h_new staged in smem; writes h fp32 + bf16 hi/lo (GEMM3 A).
// ---------------------------------------------------------------------------
#define G2_SAH 0
#define G2_SAL 10240
#define G2_SBH 20480
#define G2_SBL 40960
#define G2_HS  61440                    // float[128*68] = 34816 B
#define G2_B2S 96256                    // float[256]
#define G2_SMEM 97280

__global__ __launch_bounds__(512, 1) void gemm_gates(
    const float* __restrict__ prev_h,
    float* __restrict__ h_out)
{
    extern __shared__ __align__(16) char smem[];
    __nv_bfloat16* sAh = (__nv_bfloat16*)(smem + G2_SAH);
    __nv_bfloat16* sAl = (__nv_bfloat16*)(smem + G2_SAL);
    __nv_bfloat16* sBh = (__nv_bfloat16*)(smem + G2_SBH);
    __nv_bfloat16* sBl = (__nv_bfloat16*)(smem + G2_SBL);
    float* h_s  = (float*)(smem + G2_HS);       // stride 68
    float* b2_s = (float*)(smem + G2_B2S);

    const int t = threadIdx.x, wid = t >> 5, lane = t & 31;
    const size_t bm = (size_t)blockIdx.x * 128;
    const int wm = (wid >> 2) * 32, wn = (wid & 3) * 64;
    const uint32_t ah = smem_to_u32(sAh), al = smem_to_u32(sAl);
    const uint32_t bh = smem_to_u32(sBh), bl = smem_to_u32(sBl);

    const int a_m = (lane & 7) + ((lane >> 3) & 1) * 8;
    const int a_k = ((lane >> 4) & 1) * 8;
    const int b_n = (lane & 7) + ((lane >> 4) & 1) * 8;
    const int b_k = ((lane >> 3) & 1) * 8;

    // preload prev_h tile (fp32) + biases
    #pragma unroll
    for (int i = 0; i < 4; i++) {
        int idx = t + i * 512;               // 0..2047 float4
        int row = idx >> 4, q = idx & 15;
        float4 v = *(const float4*)(prev_h + (bm + row) * RNN_H + q * 4);
        *(float4*)(h_s + row * 68 + q * 4) = v;
    }
    if (t < 256) b2_s[t] = g_b2[t];

    float acc[2][8][4];
    #pragma unroll
    for (int mt = 0; mt < 2; mt++)
        #pragma unroll
        for (int nt = 0; nt < 8; nt++)
            #pragma unroll
            for (int q = 0; q < 4; q++) acc[mt][nt][q] = 0.0f;

    for (int c = 0; c < 4; c++) {
        {   // A chunk: 512 uint4, 1/thread
            int row = t >> 2, q = t & 3;
            ((uint4*)(sAh + row * TS + q * 8))[0] =
                ((const uint4*)g_A2h)[(bm + row) * 16 + c * 4 + q];
            ((uint4*)(sAl + row * TS + q * 8))[0] =
                ((const uint4*)g_A2l)[(bm + row) * 16 + c * 4 + q];
        }
        #pragma unroll
        for (int i = 0; i < 2; i++) {   // B chunk: 1024 uint4, 2/thread
            int idx = t + i * 512;
            int row = idx >> 2, q = idx & 3;
            ((uint4*)(sBh + row * TS + q * 8))[0] = ((const uint4*)g_B2h)[row * 16 + c * 4 + q];
            ((uint4*)(sBl + row * TS + q * 8))[0] = ((const uint4*)g_B2l)[row * 16 + c * 4 + q];
        }
        __syncthreads();

        #pragma unroll
        for (int kk = 0; kk < 2; kk++) {
            uint32_t fAh[2][4], fAl[2][4];
            #pragma unroll
            for (int mt = 0; mt < 2; mt++) {
                uint32_t off = (uint32_t)(((wm + mt * 16 + a_m) * TS + kk * 16 + a_k) * 2);
                ldmx4(fAh[mt], ah + off);
                ldmx4(fAl[mt], al + off);
            }
            #pragma unroll
            for (int ntg = 0; ntg < 4; ntg++) {
                uint32_t fBh[4], fBl[4];
                uint32_t off = (uint32_t)(((wn + ntg * 16 + b_n) * TS + kk * 16 + b_k) * 2);
                ldmx4(fBh, bh + off);
                ldmx4(fBl, bl + off);
                #pragma unroll
                for (int mt = 0; mt < 2; mt++)
                    #pragma unroll
                    for (int p = 0; p < 2; p++) {
                        float* a = acc[mt][ntg * 2 + p];
                        mma16816(a, fAh[mt], &fBh[p * 2]);
                        mma16816(a, fAh[mt], &fBl[p * 2]);
                        mma16816(a, fAl[mt], &fBh[p * 2]);
                    }
            }
        }
        __syncthreads();
    }

    // ---- fused GRU elementwise ----
    const int fr = lane >> 2, fc = (lane & 3) * 2;
    #pragma unroll
    for (int mt = 0; mt < 2; mt++) {
        #pragma unroll
        for (int nt = 0; nt < 8; nt++) {
            int n = wn + nt * 8 + fc;
            float v0 = acc[mt][nt][0] + b2_s[n];
            float v1 = acc[mt][nt][1] + b2_s[n + 1];
            float v2 = acc[mt][nt][2] + b2_s[n];
            float v3 = acc[mt][nt][3] + b2_s[n + 1];
            float p0 = __shfl_xor_sync(0xFFFFFFFF, v0, 1);
            float p1 = __shfl_xor_sync(0xFFFFFFFF, v1, 1);
            float p2 = __shfl_xor_sync(0xFFFFFFFF, v2, 1);
            float p3 = __shfl_xor_sync(0xFFFFFFFF, v3, 1);
            int j = n >> 2;
            bool is01 = ((n & 2) == 0);
            float rs, zs, nxs, nhs;
            int mrow;
            if (is01) { rs = v0; zs = v1; nxs = p0; nhs = p1; mrow = wm + mt * 16 + fr; }
            else      { rs = p2; zs = p3; nxs = v2; nhs = v3; mrow = wm + mt * 16 + fr + 8; }
            float r = sigf(rs), z = sigf(zs);
            float nn = tanhf(nxs + r * nhs);
            float hp = h_s[mrow * 68 + j];
            h_s[mrow * 68 + j] = (1.0f - z) * nn + z * hp;
        }
    }
    __syncthreads();

    // ---- coalesced writeout: h fp32 + hi/lo bf16 ----
    #pragma unroll
    for (int i = 0; i < 4; i++) {
        int idx = t + i * 512;
        int row = idx >> 4, q = idx & 15;
        float4 v = *(const float4*)(h_s + row * 68 + q * 4);
        *(float4*)(h_out + (bm + row) * RNN_H + q * 4) = v;
    }
    #pragma unroll
    for (int i = 0; i < 2; i++) {
        int idx = t + i * 512;                  // 0..1023
        int row = idx >> 3, q = idx & 7;        // q: 8-elem group
        const float* hp = h_s + row * 68 + q * 8;
        __nv_bfloat16 hi[8], lo[8];
        #pragma unroll
        for (int e = 0; e < 8; e++) split_bf16(hp[e], hi[e], lo[e]);
        *(uint4*)(g_Ah + (bm + row) * RNN_H + q * 8) = *(uint4*)hi;
        *(uint4*)(g_Al + (bm + row) * RNN_H + q * 8) = *(uint4*)lo;
    }
}

// ---------------------------------------------------------------------------
// GEMM3: logits = h_new @ W_lin^T + b_lin (unchanged from R6, proven)
// ---------------------------------------------------------------------------
#define NCHUNK (FLAT_H / 32)

__global__ __launch_bounds__(256) void gemm_mma(
    const float* __restrict__ bias, float* __restrict__ C)
{
    __shared__ __align__(16) __nv_bfloat16 sAh[128 * TS];
    __shared__ __align__(16) __nv_bfloat16 sAl[128 * TS];
    __shared__ __align__(16) __nv_bfloat16 sBh[128 * TS];
    __shared__ __align__(16) __nv_bfloat16 sBl[128 * TS];

    const int t = threadIdx.x, wid = t >> 5, lane = t & 31;
    const int bn = blockIdx.x * 128, bm = blockIdx.y * 128;
    const int wm = (wid >> 2) * 64, wn = (wid & 3) * 32;
    const uint32_t ah = smem_to_u32(sAh), al = smem_to_u32(sAl);
    const uint32_t bh = smem_to_u32(sBh), bl = smem_to_u32(sBl);

    const int a_m = (lane & 7) + ((lane >> 3) & 1) * 8;
    const int a_k = ((lane >> 4) & 1) * 8;
    const int b_n = (lane & 7) + ((lane >> 4) & 1) * 8;
    const int b_k = ((lane >> 3) & 1) * 8;

    float acc[4][4][4];
    #pragma unroll
    for (int mt = 0; mt < 4; mt++)
        #pragma unroll
        for (int ns = 0; ns < 4; ns++)
            #pragma unroll
            for (int q = 0; q < 4; q++) acc[mt][ns][q] = 0.0f;

    const uint4* gAh = (const uint4*)g_Ah;
    const uint4* gAl = (const uint4*)g_Al;
    const uint4* gBh = (const uint4*)g_Bh;
    const uint4* gBl = (const uint4*)g_Bl;

    for (int c = 0; c < NCHUNK; c++) {
        #pragma unroll
        for (int i = 0; i < 2; i++) {
            int idx = t + i * 256;
            int row = idx >> 2, q = idx & 3;
            size_t ga = (size_t)(bm + row) * 128 + c * 4 + q;
            size_t gb = (size_t)(bn + row) * 128 + c * 4 + q;
            int so = row * TS + q * 8;
            ((uint4*)(sAh + so))[0] = gAh[ga];
            ((uint4*)(sAl + so))[0] = gAl[ga];
            ((uint4*)(sBh + so))[0] = gBh[gb];
            ((uint4*)(sBl + so))[0] = gBl[gb];
        }
        __syncthreads();

        #pragma unroll
        for (int kk = 0; kk < 2; kk++) {
            const int akcol = kk * 16 + a_k;
            const int bkcol = kk * 16 + b_k;
            uint32_t fAh[4][4], fAl[4][4];
            #pragma unroll
            for (int mt = 0; mt < 4; mt++) {
                uint32_t off = (uint32_t)(((wm + mt * 16 + a_m) * TS + akcol) * 2);
                ldmx4(fAh[mt], ah + off);
                ldmx4(fAl[mt], al + off);
            }
            uint32_t fBh[2][4], fBl[2][4];
            #pragma unroll
            for (int nt = 0; nt < 2; nt++) {
                uint32_t off = (uint32_t)(((wn + nt * 16 + b_n) * TS + bkcol) * 2);
                ldmx4(fBh[nt], bh + off);
                ldmx4(fBl[nt], bl + off);
            }
            #pragma unroll
            for (int mt = 0; mt < 4; mt++)
                #pragma unroll
                for (int ns = 0; ns < 4; ns++) {
                    const uint32_t* bhp = &fBh[ns >> 1][(ns & 1) * 2];
                    const uint32_t* blp = &fBl[ns >> 1][(ns & 1) * 2];
                    mma16816(acc[mt][ns], fAh[mt], bhp);
                    mma16816(acc[mt][ns], fAh[mt], blp);
                    mma16816(acc[mt][ns], fAl[mt], bhp);
                }
        }
        __syncthreads();
    }

    const int fr = lane >> 2, fc = (lane & 3) * 2;
    #pragma unroll
    for (int mt = 0; mt < 4; mt++)
        #pragma unroll
        for (int ns = 0; ns < 4; ns++) {
            int col = bn + wn + ns * 8 + fc;
            float2 bv = *(const float2*)(bias + col);
            int r0 = bm + wm + mt * 16 + fr;
            *(float2*)(C + (size_t)r0 * OUT_DIM + col) =
                make_float2(acc[mt][ns][0] + bv.x, acc[mt][ns][1] + bv.y);
            *(float2*)(C + (size_t)(r0 + 8) * OUT_DIM + col) =
                make_float2(acc[mt][ns][2] + bv.x, acc[mt][ns][3] + bv.y);
        }
}

// ---------------------------------------------------------------------------
extern "C" void kernel_launch(void* const* d_in, const int* in_sizes, int n_in,
                              void* d_out, int out_size) {
    const float* x     = (const float*)d_in[0];
    const int*   ei    = (const int*)  d_in[1];
    const float* ph    = (const float*)d_in[2];
    const float* Wg    = (const float*)d_in[3];
    const float* bg    = (const float*)d_in[4];
    const float* W_ih  = (const float*)d_in[5];
    const float* W_hh  = (const float*)d_in[6];
    const float* b_ih  = (const float*)d_in[7];
    const float* b_hh  = (const float*)d_in[8];
    const float* W_lin = (const float*)d_in[9];
    const float* b_lin = (const float*)d_in[10];

    float* out = (float*)d_out;
    bool has_nh = (out_size >= NUM_ENVS * (OUT_DIM + FLAT_H));
    float* hdst;
    if (has_nh) {
        hdst = out + (size_t)NUM_ENVS * OUT_DIM;
    } else {
        cudaGetSymbolAddress((void**)&hdst, g_hbuf);
    }

    static bool init = false;
    if (!init) {
        cudaFuncSetAttribute(gemm_gates, cudaFuncAttributeMaxDynamicSharedMemorySize,
                             G2_SMEM);
        init = true;
    }

    pack_w_kernel<<<(PK_TOT + 255) / 256, 256>>>(Wg, W_ih, W_hh, b_ih, b_hh, W_lin);
    gemm_xw<<<NNODE / 128, 256>>>(x);
    scatter_kernel<<<NUM_ENVS, 128>>>(ei, ph, bg);
    gemm_gates<<<NNODE / 128, 512, G2_SMEM>>>(ph, hdst);
    gemm_mma<<<dim3(OUT_DIM / 128, NUM_ENVS / 128), 256>>>(b_lin, out);
}

// round 8
// speedup vs baseline: 2.2077x; 1.0628x over previous
#include <cuda_runtime.h>
#include <cuda_bf16.h>
#include <math.h>
#include <cstdint>

#define NUM_ENVS 16384
#define NUM_AGENTS 16
#define IN_DIM 128
#define GCN_H 64
#define RNN_H 64
#define E_PER_GRAPH 128
#define OUT_DIM 512
#define FLAT_H (NUM_AGENTS * RNN_H)      // 1024
#define NNODE ((size_t)NUM_ENVS * NUM_AGENTS)   // 262144

// ---------------- static device scratch -------------------------------------
__device__ float  g_hbuf[(size_t)NUM_ENVS * FLAT_H];
__device__ float  g_xw[NNODE * GCN_H];
__device__ __align__(16) __nv_bfloat16 g_A2h[NNODE * 128];
__device__ __align__(16) __nv_bfloat16 g_A2l[NNODE * 128];
__device__ __align__(16) __nv_bfloat16 g_Ah[NNODE * RNN_H];
__device__ __align__(16) __nv_bfloat16 g_Al[NNODE * RNN_H];
__device__ __align__(16) __nv_bfloat16 g_Wgth[GCN_H * IN_DIM];
__device__ __align__(16) __nv_bfloat16 g_Wgtl[GCN_H * IN_DIM];
__device__ __align__(16) __nv_bfloat16 g_B2h[256 * 128];
__device__ __align__(16) __nv_bfloat16 g_B2l[256 * 128];
__device__ float g_b2[256];
__device__ __align__(16) __nv_bfloat16 g_Bh[(size_t)OUT_DIM * FLAT_H];
__device__ __align__(16) __nv_bfloat16 g_Bl[(size_t)OUT_DIM * FLAT_H];

// ---------------- helpers ---------------------------------------------------
__device__ __forceinline__ uint32_t smem_to_u32(const void* p) {
    uint32_t a;
    asm("{ .reg .u64 t; cvta.to.shared.u64 t, %1; cvt.u32.u64 %0, t; }" : "=r"(a) : "l"(p));
    return a;
}
__device__ __forceinline__ float sigf(float v) { return 1.0f / (1.0f + expf(-v)); }

__device__ __forceinline__ void ldmx4(uint32_t* r, uint32_t addr) {
    asm volatile("ldmatrix.sync.aligned.m8n8.x4.shared.b16 {%0,%1,%2,%3}, [%4];"
                 : "=r"(r[0]), "=r"(r[1]), "=r"(r[2]), "=r"(r[3]) : "r"(addr));
}
__device__ __forceinline__ void mma16816(float* d, const uint32_t* a, const uint32_t* b) {
    asm volatile("mma.sync.aligned.m16n8k16.row.col.f32.bf16.bf16.f32 "
                 "{%0,%1,%2,%3}, {%4,%5,%6,%7}, {%8,%9}, {%0,%1,%2,%3};"
                 : "+f"(d[0]), "+f"(d[1]), "+f"(d[2]), "+f"(d[3])
                 : "r"(a[0]), "r"(a[1]), "r"(a[2]), "r"(a[3]), "r"(b[0]), "r"(b[1]));
}
__device__ __forceinline__ void split_bf16(float f, __nv_bfloat16& hi, __nv_bfloat16& lo) {
    hi = __float2bfloat16(f);
    lo = __float2bfloat16(f - __bfloat162float(hi));
}
__device__ __forceinline__ void cp16(uint32_t dst, const void* src) {
    asm volatile("cp.async.cg.shared.global [%0], [%1], 16;" :: "r"(dst), "l"(src));
}
#define CP_COMMIT() asm volatile("cp.async.commit_group;")
#define CP_WAIT(N)  asm volatile("cp.async.wait_group %0;" :: "n"(N))

// ---------------------------------------------------------------------------
// pack weights
// ---------------------------------------------------------------------------
#define PK_WGT (GCN_H * IN_DIM)
#define PK_B2  (256 * 128)
#define PK_WL  (OUT_DIM * FLAT_H)
#define PK_TOT (PK_WGT + PK_B2 + 256 + PK_WL)

__global__ void pack_w_kernel(const float* __restrict__ Wg,
                              const float* __restrict__ W_ih,
                              const float* __restrict__ W_hh,
                              const float* __restrict__ b_ih,
                              const float* __restrict__ b_hh,
                              const float* __restrict__ Wl) {
    int idx = blockIdx.x * 256 + threadIdx.x;
    if (idx < PK_WGT) {
        int n = idx >> 7, k = idx & 127;
        split_bf16(Wg[k * GCN_H + n], g_Wgth[idx], g_Wgtl[idx]);
    } else if (idx < PK_WGT + PK_B2) {
        int r = idx - PK_WGT;
        int n = r >> 7, k = r & 127;
        int j = n >> 2, g = n & 3;
        float w = 0.0f;
        if (g == 0)      w = (k < 64) ? W_ih[j * 64 + k]         : W_hh[j * 64 + (k - 64)];
        else if (g == 1) w = (k < 64) ? W_ih[(64 + j) * 64 + k]  : W_hh[(64 + j) * 64 + (k - 64)];
        else if (g == 2) w = (k < 64) ? W_ih[(128 + j) * 64 + k] : 0.0f;
        else             w = (k < 64) ? 0.0f                     : W_hh[(128 + j) * 64 + (k - 64)];
        split_bf16(w, g_B2h[r], g_B2l[r]);
    } else if (idx < PK_WGT + PK_B2 + 256) {
        int n = idx - PK_WGT - PK_B2;
        int j = n >> 2, g = n & 3;
        float b;
        if (g == 0)      b = b_ih[j] + b_hh[j];
        else if (g == 1) b = b_ih[64 + j] + b_hh[64 + j];
        else if (g == 2) b = b_ih[128 + j];
        else             b = b_hh[128 + j];
        g_b2[n] = b;
    } else if (idx < PK_TOT) {
        int r = idx - PK_WGT - PK_B2 - 256;
        split_bf16(Wl[r], g_Bh[r], g_Bl[r]);
    }
}

// ---------------------------------------------------------------------------
// GEMM1: xw = x @ Wgcn  (unchanged from R7, proven)
// ---------------------------------------------------------------------------
#define TS 40

__global__ __launch_bounds__(256) void gemm_xw(const float* __restrict__ x) {
    __shared__ __align__(16) __nv_bfloat16 sAh[128 * TS];
    __shared__ __align__(16) __nv_bfloat16 sAl[128 * TS];
    __shared__ __align__(16) __nv_bfloat16 sBh[64 * TS];
    __shared__ __align__(16) __nv_bfloat16 sBl[64 * TS];

    const int t = threadIdx.x, wid = t >> 5, lane = t & 31;
    const size_t bm = (size_t)blockIdx.x * 128;
    const int wm = (wid >> 1) * 32, wn = (wid & 1) * 32;
    const uint32_t ah = smem_to_u32(sAh), al = smem_to_u32(sAl);
    const uint32_t bh = smem_to_u32(sBh), bl = smem_to_u32(sBl);

    const int a_m = (lane & 7) + ((lane >> 3) & 1) * 8;
    const int a_k = ((lane >> 4) & 1) * 8;
    const int b_n = (lane & 7) + ((lane >> 4) & 1) * 8;
    const int b_k = ((lane >> 3) & 1) * 8;

    float acc[2][4][4];
    #pragma unroll
    for (int mt = 0; mt < 2; mt++)
        #pragma unroll
        for (int nt = 0; nt < 4; nt++)
            #pragma unroll
            for (int q = 0; q < 4; q++) acc[mt][nt][q] = 0.0f;

    for (int c = 0; c < 4; c++) {
        #pragma unroll
        for (int i = 0; i < 4; i++) {
            int idx = t + i * 256;
            int row = idx >> 3, q = idx & 7;
            float4 v = *(const float4*)(x + (bm + row) * IN_DIM + c * 32 + q * 4);
            __nv_bfloat16 h0, l0, h1, l1, h2, l2, h3, l3;
            split_bf16(v.x, h0, l0); split_bf16(v.y, h1, l1);
            split_bf16(v.z, h2, l2); split_bf16(v.w, h3, l3);
            __nv_bfloat162* ph = (__nv_bfloat162*)(sAh + row * TS + q * 4);
            __nv_bfloat162* pl = (__nv_bfloat162*)(sAl + row * TS + q * 4);
            ph[0] = __nv_bfloat162(h0, h1); ph[1] = __nv_bfloat162(h2, h3);
            pl[0] = __nv_bfloat162(l0, l1); pl[1] = __nv_bfloat162(l2, l3);
        }
        {
            int row = t >> 2, q = t & 3;
            ((uint4*)(sBh + row * TS + q * 8))[0] = ((const uint4*)g_Wgth)[row * 16 + c * 4 + q];
            ((uint4*)(sBl + row * TS + q * 8))[0] = ((const uint4*)g_Wgtl)[row * 16 + c * 4 + q];
        }
        __syncthreads();

        #pragma unroll
        for (int kk = 0; kk < 2; kk++) {
            uint32_t fAh[2][4], fAl[2][4];
            #pragma unroll
            for (int mt = 0; mt < 2; mt++) {
                uint32_t off = (uint32_t)(((wm + mt * 16 + a_m) * TS + kk * 16 + a_k) * 2);
                ldmx4(fAh[mt], ah + off);
                ldmx4(fAl[mt], al + off);
            }
            #pragma unroll
            for (int ntg = 0; ntg < 2; ntg++) {
                uint32_t fBh[4], fBl[4];
                uint32_t off = (uint32_t)(((wn + ntg * 16 + b_n) * TS + kk * 16 + b_k) * 2);
                ldmx4(fBh, bh + off);
                ldmx4(fBl, bl + off);
                #pragma unroll
                for (int mt = 0; mt < 2; mt++)
                    #pragma unroll
                    for (int p = 0; p < 2; p++) {
                        float* a = acc[mt][ntg * 2 + p];
                        mma16816(a, fAh[mt], &fBh[p * 2]);
                        mma16816(a, fAh[mt], &fBl[p * 2]);
                        mma16816(a, fAl[mt], &fBh[p * 2]);
                    }
            }
        }
        __syncthreads();
    }

    const int fr = lane >> 2, fc = (lane & 3) * 2;
    #pragma unroll
    for (int mt = 0; mt < 2; mt++)
        #pragma unroll
        for (int nt = 0; nt < 4; nt++) {
            int n = wn + nt * 8 + fc;
            size_t r0 = bm + wm + mt * 16 + fr;
            *(float2*)(g_xw + r0 * GCN_H + n)       = make_float2(acc[mt][nt][0], acc[mt][nt][1]);
            *(float2*)(g_xw + (r0 + 8) * GCN_H + n) = make_float2(acc[mt][nt][2], acc[mt][nt][3]);
        }
}

// ---------------------------------------------------------------------------
// Scatter (unchanged from R7, proven)
// ---------------------------------------------------------------------------
__global__ __launch_bounds__(128) void scatter_kernel(
    const int* __restrict__ ei, const float* __restrict__ prev_h,
    const float* __restrict__ bg)
{
    __shared__ __align__(16) float xw_s[NUM_AGENTS * GCN_H];
    __shared__ float Adj[NUM_AGENTS * NUM_AGENTS];
    __shared__ float deg_s[NUM_AGENTS], dinv_s[NUM_AGENTS];

    const int env = blockIdx.x;
    const int t   = threadIdx.x;

    if (t < NUM_AGENTS) deg_s[t] = 1.0f;
    #pragma unroll
    for (int i = 0; i < 2; i++) Adj[t + i * 128] = 0.0f;

    #pragma unroll
    for (int i = 0; i < 2; i++)
        ((float4*)xw_s)[t + i * 128] =
            ((const float4*)(g_xw + (size_t)env * NUM_AGENTS * GCN_H))[t + i * 128];

    const int rr = ei[(size_t)env * 256 + t];
    const int cc = ei[(size_t)env * 256 + 128 + t];
    __syncthreads();

    atomicAdd(&deg_s[cc], 1.0f);
    __syncthreads();
    if (t < NUM_AGENTS) dinv_s[t] = rsqrtf(deg_s[t]);
    __syncthreads();

    atomicAdd(&Adj[cc * 16 + rr], dinv_s[rr] * dinv_s[cc]);
    if (t < NUM_AGENTS) atomicAdd(&Adj[t * 16 + t], dinv_s[t] * dinv_s[t]);
    __syncthreads();

    const int j  = t & 63;
    const int cq = t >> 6;
    float xv[NUM_AGENTS];
    #pragma unroll
    for (int r = 0; r < NUM_AGENTS; r++) xv[r] = xw_s[r * GCN_H + j];
    const float bgj = bg[j];

    #pragma unroll
    for (int i = 0; i < 8; i++) {
        int c = cq * 8 + i;
        float s = 0.0f;
        #pragma unroll
        for (int r = 0; r < NUM_AGENTS; r++) s += Adj[c * 16 + r] * xv[r];
        s += bgj;
        size_t node = (size_t)env * NUM_AGENTS + c;
        __nv_bfloat16 hi, lo;
        split_bf16(s, hi, lo);
        g_A2h[node * 128 + j] = hi;
        g_A2l[node * 128 + j] = lo;
    }

    #pragma unroll
    for (int i = 0; i < 2; i++) {
        int f4 = t + i * 128;
        float4 v = ((const float4*)(prev_h + (size_t)env * FLAT_H))[f4];
        int row = f4 >> 4, jj = (f4 & 15) * 4;
        size_t node = (size_t)env * NUM_AGENTS + row;
        __nv_bfloat16 h0, l0, h1, l1, h2, l2, h3, l3;
        split_bf16(v.x, h0, l0); split_bf16(v.y, h1, l1);
        split_bf16(v.z, h2, l2); split_bf16(v.w, h3, l3);
        __nv_bfloat162* ph = (__nv_bfloat162*)(g_A2h + node * 128 + 64 + jj);
        __nv_bfloat162* pl = (__nv_bfloat162*)(g_A2l + node * 128 + 64 + jj);
        ph[0] = __nv_bfloat162(h0, h1); ph[1] = __nv_bfloat162(h2, h3);
        pl[0] = __nv_bfloat162(l0, l1); pl[1] = __nv_bfloat162(l2, l3);
    }
}

// ---------------------------------------------------------------------------
// GEMM2 (gates + GRU) — now cp.async double-buffered.
// BM=128, BN=256, BK=32, 512 thr. Stage = {Ah,Al,Bh,Bl} = 61440 B.
// ---------------------------------------------------------------------------
#define G2_STG  61440
#define G2_AH   0
#define G2_AL   10240
#define G2_BH   20480
#define G2_BL   40960
#define G2_HS   (2 * G2_STG)                 // 122880: float[128*68]
#define G2_B2S  (G2_HS + 34816)              // 157696
#define G2_SMEM (G2_B2S + 1024)              // 158720

__global__ __launch_bounds__(512, 1) void gemm_gates(
    const float* __restrict__ prev_h,
    float* __restrict__ h_out)
{
    extern __shared__ __align__(16) char smem[];
    const uint32_t sb = smem_to_u32(smem);
    float* h_s  = (float*)(smem + G2_HS);
    float* b2_s = (float*)(smem + G2_B2S);

    const int t = threadIdx.x, wid = t >> 5, lane = t & 31;
    const size_t bm = (size_t)blockIdx.x * 128;
    const int wm = (wid >> 2) * 32, wn = (wid & 3) * 64;

    const int a_m = (lane & 7) + ((lane >> 3) & 1) * 8;
    const int a_k = ((lane >> 4) & 1) * 8;
    const int b_n = (lane & 7) + ((lane >> 4) & 1) * 8;
    const int b_k = ((lane >> 3) & 1) * 8;

    // per-thread load coordinates
    const int la_row = t >> 2, la_q = t & 3;                   // A: 512 slots

    // issue chunk c into stage s
    auto issue = [&](int c, int s) {
        uint32_t base = sb + s * G2_STG;
        cp16(base + G2_AH + (uint32_t)(la_row * TS + la_q * 8) * 2,
             g_A2h + (bm + la_row) * 128 + c * 32 + la_q * 8);
        cp16(base + G2_AL + (uint32_t)(la_row * TS + la_q * 8) * 2,
             g_A2l + (bm + la_row) * 128 + c * 32 + la_q * 8);
        #pragma unroll
        for (int i = 0; i < 2; i++) {
            int idx = t + i * 512;
            int row = idx >> 2, q = idx & 3;
            cp16(base + G2_BH + (uint32_t)(row * TS + q * 8) * 2,
                 g_B2h + row * 128 + c * 32 + q * 8);
            cp16(base + G2_BL + (uint32_t)(row * TS + q * 8) * 2,
                 g_B2l + row * 128 + c * 32 + q * 8);
        }
    };

    // prefetch chunk 0
    issue(0, 0);
    CP_COMMIT();

    // preload prev_h tile + biases (overlaps with async loads)
    #pragma unroll
    for (int i = 0; i < 4; i++) {
        int idx = t + i * 512;
        int row = idx >> 4, q = idx & 15;
        float4 v = *(const float4*)(prev_h + (bm + row) * RNN_H + q * 4);
        *(float4*)(h_s + row * 68 + q * 4) = v;
    }
    if (t < 256) b2_s[t] = g_b2[t];

    float acc[2][8][4];
    #pragma unroll
    for (int mt = 0; mt < 2; mt++)
        #pragma unroll
        for (int nt = 0; nt < 8; nt++)
            #pragma unroll
            for (int q = 0; q < 4; q++) acc[mt][nt][q] = 0.0f;

    for (int c = 0; c < 4; c++) {
        if (c + 1 < 4) {
            issue(c + 1, (c + 1) & 1);
            CP_COMMIT();
            CP_WAIT(1);
        } else {
            CP_WAIT(0);
        }
        __syncthreads();

        const uint32_t base = sb + (c & 1) * G2_STG;
        #pragma unroll
        for (int kk = 0; kk < 2; kk++) {
            uint32_t fAh[2][4], fAl[2][4];
            #pragma unroll
            for (int mt = 0; mt < 2; mt++) {
                uint32_t off = (uint32_t)(((wm + mt * 16 + a_m) * TS + kk * 16 + a_k) * 2);
                ldmx4(fAh[mt], base + G2_AH + off);
                ldmx4(fAl[mt], base + G2_AL + off);
            }
            #pragma unroll
            for (int ntg = 0; ntg < 4; ntg++) {
                uint32_t fBh[4], fBl[4];
                uint32_t off = (uint32_t)(((wn + ntg * 16 + b_n) * TS + kk * 16 + b_k) * 2);
                ldmx4(fBh, base + G2_BH + off);
                ldmx4(fBl, base + G2_BL + off);
                #pragma unroll
                for (int mt = 0; mt < 2; mt++)
                    #pragma unroll
                    for (int p = 0; p < 2; p++) {
                        float* a = acc[mt][ntg * 2 + p];
                        mma16816(a, fAh[mt], &fBh[p * 2]);
                        mma16816(a, fAh[mt], &fBl[p * 2]);
                        mma16816(a, fAl[mt], &fBh[p * 2]);
                    }
            }
        }
        __syncthreads();   // all warps done with stage (c&1) before it's re-filled
    }

    // ---- fused GRU elementwise ----
    const int fr = lane >> 2, fc = (lane & 3) * 2;
    #pragma unroll
    for (int mt = 0; mt < 2; mt++) {
        #pragma unroll
        for (int nt = 0; nt < 8; nt++) {
            int n = wn + nt * 8 + fc;
            float v0 = acc[mt][nt][0] + b2_s[n];
            float v1 = acc[mt][nt][1] + b2_s[n + 1];
            float v2 = acc[mt][nt][2] + b2_s[n];
            float v3 = acc[mt][nt][3] + b2_s[n + 1];
            float p0 = __shfl_xor_sync(0xFFFFFFFF, v0, 1);
            float p1 = __shfl_xor_sync(0xFFFFFFFF, v1, 1);
            float p2 = __shfl_xor_sync(0xFFFFFFFF, v2, 1);
            float p3 = __shfl_xor_sync(0xFFFFFFFF, v3, 1);
            int j = n >> 2;
            bool is01 = ((n & 2) == 0);
            float rs, zs, nxs, nhs;
            int mrow;
            if (is01) { rs = v0; zs = v1; nxs = p0; nhs = p1; mrow = wm + mt * 16 + fr; }
            else      { rs = p2; zs = p3; nxs = v2; nhs = v3; mrow = wm + mt * 16 + fr + 8; }
            float r = sigf(rs), z = sigf(zs);
            float nn = tanhf(nxs + r * nhs);
            float hp = h_s[mrow * 68 + j];
            h_s[mrow * 68 + j] = (1.0f - z) * nn + z * hp;
        }
    }
    __syncthreads();

    // ---- coalesced writeout ----
    #pragma unroll
    for (int i = 0; i < 4; i++) {
        int idx = t + i * 512;
        int row = idx >> 4, q = idx & 15;
        float4 v = *(const float4*)(h_s + row * 68 + q * 4);
        *(float4*)(h_out + (bm + row) * RNN_H + q * 4) = v;
    }
    #pragma unroll
    for (int i = 0; i < 2; i++) {
        int idx = t + i * 512;
        int row = idx >> 3, q = idx & 7;
        const float* hp = h_s + row * 68 + q * 8;
        __nv_bfloat16 hi[8], lo[8];
        #pragma unroll
        for (int e = 0; e < 8; e++) split_bf16(hp[e], hi[e], lo[e]);
        *(uint4*)(g_Ah + (bm + row) * RNN_H + q * 8) = *(uint4*)hi;
        *(uint4*)(g_Al + (bm + row) * RNN_H + q * 8) = *(uint4*)lo;
    }
}

// ---------------------------------------------------------------------------
// GEMM3 — cp.async double-buffered, 2 CTAs/SM.
// Stage = {Ah,Al,Bh,Bl} each 10240 B = 40960 B; x2 = 81920 dynamic.
// ---------------------------------------------------------------------------
#define G3_STG 40960
#define G3_AH  0
#define G3_AL  10240
#define G3_BH  20480
#define G3_BL  30720
#define G3_SMEM (2 * G3_STG)
#define NCHUNK (FLAT_H / 32)

__global__ __launch_bounds__(256, 2) void gemm_mma(
    const float* __restrict__ bias, float* __restrict__ C)
{
    extern __shared__ __align__(16) char smem[];
    const uint32_t sb = smem_to_u32(smem);

    const int t = threadIdx.x, wid = t >> 5, lane = t & 31;
    const int bn = blockIdx.x * 128, bm = blockIdx.y * 128;
    const int wm = (wid >> 2) * 64, wn = (wid & 3) * 32;

    const int a_m = (lane & 7) + ((lane >> 3) & 1) * 8;
    const int a_k = ((lane >> 4) & 1) * 8;
    const int b_n = (lane & 7) + ((lane >> 4) & 1) * 8;
    const int b_k = ((lane >> 3) & 1) * 8;

    auto issue = [&](int c, int s) {
        uint32_t base = sb + s * G3_STG;
        #pragma unroll
        for (int i = 0; i < 2; i++) {
            int idx = t + i * 256;
            int row = idx >> 2, q = idx & 3;
            uint32_t so = (uint32_t)(row * TS + q * 8) * 2;
            cp16(base + G3_AH + so, g_Ah + (size_t)(bm + row) * FLAT_H + c * 32 + q * 8);
            cp16(base + G3_AL + so, g_Al + (size_t)(bm + row) * FLAT_H + c * 32 + q * 8);
            cp16(base + G3_BH + so, g_Bh + (size_t)(bn + row) * FLAT_H + c * 32 + q * 8);
            cp16(base + G3_BL + so, g_Bl + (size_t)(bn + row) * FLAT_H + c * 32 + q * 8);
        }
    };

    float acc[4][4][4];
    #pragma unroll
    for (int mt = 0; mt < 4; mt++)
        #pragma unroll
        for (int ns = 0; ns < 4; ns++)
            #pragma unroll
            for (int q = 0; q < 4; q++) acc[mt][ns][q] = 0.0f;

    issue(0, 0);
    CP_COMMIT();

    for (int c = 0; c < NCHUNK; c++) {
        if (c + 1 < NCHUNK) {
            issue(c + 1, (c + 1) & 1);
            CP_COMMIT();
            CP_WAIT(1);
        } else {
            CP_WAIT(0);
        }
        __syncthreads();

        const uint32_t base = sb + (c & 1) * G3_STG;
        #pragma unroll
        for (int kk = 0; kk < 2; kk++) {
            const int akcol = kk * 16 + a_k;
            const int bkcol = kk * 16 + b_k;
            uint32_t fAh[4][4], fAl[4][4];
            #pragma unroll
            for (int mt = 0; mt < 4; mt++) {
                uint32_t off = (uint32_t)(((wm + mt * 16 + a_m) * TS + akcol) * 2);
                ldmx4(fAh[mt], base + G3_AH + off);
                ldmx4(fAl[mt], base + G3_AL + off);
            }
            uint32_t fBh[2][4], fBl[2][4];
            #pragma unroll
            for (int nt = 0; nt < 2; nt++) {
                uint32_t off = (uint32_t)(((wn + nt * 16 + b_n) * TS + bkcol) * 2);
                ldmx4(fBh[nt], base + G3_BH + off);
                ldmx4(fBl[nt], base + G3_BL + off);
            }
            #pragma unroll
            for (int mt = 0; mt < 4; mt++)
                #pragma unroll
                for (int ns = 0; ns < 4; ns++) {
                    const uint32_t* bhp = &fBh[ns >> 1][(ns & 1) * 2];
                    const uint32_t* blp = &fBl[ns >> 1][(ns & 1) * 2];
                    mma16816(acc[mt][ns], fAh[mt], bhp);
                    mma16816(acc[mt][ns], fAh[mt], blp);
                    mma16816(acc[mt][ns], fAl[mt], bhp);
                }
        }
        __syncthreads();
    }

    const int fr = lane >> 2, fc = (lane & 3) * 2;
    #pragma unroll
    for (int mt = 0; mt < 4; mt++)
        #pragma unroll
        for (int ns = 0; ns < 4; ns++) {
            int col = bn + wn + ns * 8 + fc;
            float2 bv = *(const float2*)(bias + col);
            int r0 = bm + wm + mt * 16 + fr;
            *(float2*)(C + (size_t)r0 * OUT_DIM + col) =
                make_float2(acc[mt][ns][0] + bv.x, acc[mt][ns][1] + bv.y);
            *(float2*)(C + (size_t)(r0 + 8) * OUT_DIM + col) =
                make_float2(acc[mt][ns][2] + bv.x, acc[mt][ns][3] + bv.y);
        }
}

// ---------------------------------------------------------------------------
extern "C" void kernel_launch(void* const* d_in, const int* in_sizes, int n_in,
                              void* d_out, int out_size) {
    const float* x     = (const float*)d_in[0];
    const int*   ei    = (const int*)  d_in[1];
    const float* ph    = (const float*)d_in[2];
    const float* Wg    = (const float*)d_in[3];
    const float* bg    = (const float*)d_in[4];
    const float* W_ih  = (const float*)d_in[5];
    const float* W_hh  = (const float*)d_in[6];
    const float* b_ih  = (const float*)d_in[7];
    const float* b_hh  = (const float*)d_in[8];
    const float* W_lin = (const float*)d_in[9];
    const float* b_lin = (const float*)d_in[10];

    float* out = (float*)d_out;
    bool has_nh = (out_size >= NUM_ENVS * (OUT_DIM + FLAT_H));
    float* hdst;
    if (has_nh) {
        hdst = out + (size_t)NUM_ENVS * OUT_DIM;
    } else {
        cudaGetSymbolAddress((void**)&hdst, g_hbuf);
    }

    static bool init = false;
    if (!init) {
        cudaFuncSetAttribute(gemm_gates, cudaFuncAttributeMaxDynamicSharedMemorySize,
                             G2_SMEM);
        cudaFuncSetAttribute(gemm_mma, cudaFuncAttributeMaxDynamicSharedMemorySize,
                             G3_SMEM);
        init = true;
    }

    pack_w_kernel<<<(PK_TOT + 255) / 256, 256>>>(Wg, W_ih, W_hh, b_ih, b_hh, W_lin);
    gemm_xw<<<NNODE / 128, 256>>>(x);
    scatter_kernel<<<NUM_ENVS, 128>>>(ei, ph, bg);
    gemm_gates<<<NNODE / 128, 512, G2_SMEM>>>(ph, hdst);
    gemm_mma<<<dim3(OUT_DIM / 128, NUM_ENVS / 128), 256, G3_SMEM>>>(b_lin, out);
}

// round 9
// speedup vs baseline: 3.7137x; 1.6821x over previous
#include <cuda_runtime.h>
#include <cuda_fp16.h>
#include <math.h>
#include <cstdint>

#define NUM_ENVS 16384
#define NUM_AGENTS 16
#define IN_DIM 128
#define GCN_H 64
#define RNN_H 64
#define E_PER_GRAPH 128
#define OUT_DIM 512
#define FLAT_H (NUM_AGENTS * RNN_H)      // 1024
#define NNODE ((size_t)NUM_ENVS * NUM_AGENTS)   // 262144

// ---------------- static device scratch -------------------------------------
__device__ float  g_hbuf[(size_t)NUM_ENVS * FLAT_H];
__device__ float  g_xw[NNODE * GCN_H];
__device__ __align__(16) __half g_A2[NNODE * 128];        // [gcn | prev_h] fp16
__device__ __align__(16) __half g_A3[NNODE * RNN_H];      // h_new fp16 (GEMM3 A)
__device__ __align__(16) __half g_Wgt[GCN_H * IN_DIM];    // Wgcn^T fp16
__device__ __align__(16) __half g_B2[256 * 128];          // gate weights fp16
__device__ float g_b2[256];
__device__ __align__(16) __half g_B3[(size_t)OUT_DIM * FLAT_H];  // W_lin fp16

// ---------------- helpers ---------------------------------------------------
__device__ __forceinline__ uint32_t smem_to_u32(const void* p) {
    uint32_t a;
    asm("{ .reg .u64 t; cvta.to.shared.u64 t, %1; cvt.u32.u64 %0, t; }" : "=r"(a) : "l"(p));
    return a;
}
__device__ __forceinline__ float sigf(float v) { return 1.0f / (1.0f + expf(-v)); }

__device__ __forceinline__ void ldmx4(uint32_t* r, uint32_t addr) {
    asm volatile("ldmatrix.sync.aligned.m8n8.x4.shared.b16 {%0,%1,%2,%3}, [%4];"
                 : "=r"(r[0]), "=r"(r[1]), "=r"(r[2]), "=r"(r[3]) : "r"(addr));
}
__device__ __forceinline__ void mma16816(float* d, const uint32_t* a, const uint32_t* b) {
    asm volatile("mma.sync.aligned.m16n8k16.row.col.f32.f16.f16.f32 "
                 "{%0,%1,%2,%3}, {%4,%5,%6,%7}, {%8,%9}, {%0,%1,%2,%3};"
                 : "+f"(d[0]), "+f"(d[1]), "+f"(d[2]), "+f"(d[3])
                 : "r"(a[0]), "r"(a[1]), "r"(a[2]), "r"(a[3]), "r"(b[0]), "r"(b[1]));
}
__device__ __forceinline__ void cp16(uint32_t dst, const void* src) {
    asm volatile("cp.async.cg.shared.global [%0], [%1], 16;" :: "r"(dst), "l"(src));
}
#define CP_COMMIT() asm volatile("cp.async.commit_group;")
#define CP_WAIT(N)  asm volatile("cp.async.wait_group %0;" :: "n"(N))

// ---------------------------------------------------------------------------
// pack weights (all fp16 single precision-pass)
// ---------------------------------------------------------------------------
#define PK_WGT (GCN_H * IN_DIM)
#define PK_B2  (256 * 128)
#define PK_WL  (OUT_DIM * FLAT_H)
#define PK_TOT (PK_WGT + PK_B2 + 256 + PK_WL)

__global__ void pack_w_kernel(const float* __restrict__ Wg,
                              const float* __restrict__ W_ih,
                              const float* __restrict__ W_hh,
                              const float* __restrict__ b_ih,
                              const float* __restrict__ b_hh,
                              const float* __restrict__ Wl) {
    int idx = blockIdx.x * 256 + threadIdx.x;
    if (idx < PK_WGT) {
        int n = idx >> 7, k = idx & 127;
        g_Wgt[idx] = __float2half_rn(Wg[k * GCN_H + n]);
    } else if (idx < PK_WGT + PK_B2) {
        int r = idx - PK_WGT;
        int n = r >> 7, k = r & 127;
        int j = n >> 2, g = n & 3;
        float w = 0.0f;
        if (g == 0)      w = (k < 64) ? W_ih[j * 64 + k]         : W_hh[j * 64 + (k - 64)];
        else if (g == 1) w = (k < 64) ? W_ih[(64 + j) * 64 + k]  : W_hh[(64 + j) * 64 + (k - 64)];
        else if (g == 2) w = (k < 64) ? W_ih[(128 + j) * 64 + k] : 0.0f;
        else             w = (k < 64) ? 0.0f                     : W_hh[(128 + j) * 64 + (k - 64)];
        g_B2[r] = __float2half_rn(w);
    } else if (idx < PK_WGT + PK_B2 + 256) {
        int n = idx - PK_WGT - PK_B2;
        int j = n >> 2, g = n & 3;
        float b;
        if (g == 0)      b = b_ih[j] + b_hh[j];
        else if (g == 1) b = b_ih[64 + j] + b_hh[64 + j];
        else if (g == 2) b = b_ih[128 + j];
        else             b = b_hh[128 + j];
        g_b2[n] = b;
    } else if (idx < PK_TOT) {
        int r = idx - PK_WGT - PK_B2 - 256;
        g_B3[r] = __float2half_rn(Wl[r]);
    }
}

// ---------------------------------------------------------------------------
// GEMM1: xw = x @ Wgcn  (fp16 single pass)
// ---------------------------------------------------------------------------
#define TS 40

__global__ __launch_bounds__(256) void gemm_xw(const float* __restrict__ x) {
    __shared__ __align__(16) __half sA[128 * TS];
    __shared__ __align__(16) __half sB[64 * TS];

    const int t = threadIdx.x, wid = t >> 5, lane = t & 31;
    const size_t bm = (size_t)blockIdx.x * 128;
    const int wm = (wid >> 1) * 32, wn = (wid & 1) * 32;
    const uint32_t ab = smem_to_u32(sA), bb = smem_to_u32(sB);

    const int a_m = (lane & 7) + ((lane >> 3) & 1) * 8;
    const int a_k = ((lane >> 4) & 1) * 8;
    const int b_n = (lane & 7) + ((lane >> 4) & 1) * 8;
    const int b_k = ((lane >> 3) & 1) * 8;

    float acc[2][4][4];
    #pragma unroll
    for (int mt = 0; mt < 2; mt++)
        #pragma unroll
        for (int nt = 0; nt < 4; nt++)
            #pragma unroll
            for (int q = 0; q < 4; q++) acc[mt][nt][q] = 0.0f;

    for (int c = 0; c < 4; c++) {
        #pragma unroll
        for (int i = 0; i < 4; i++) {
            int idx = t + i * 256;
            int row = idx >> 3, q = idx & 7;
            float4 v = *(const float4*)(x + (bm + row) * IN_DIM + c * 32 + q * 4);
            __half2* ph = (__half2*)(sA + row * TS + q * 4);
            ph[0] = __floats2half2_rn(v.x, v.y);
            ph[1] = __floats2half2_rn(v.z, v.w);
        }
        {
            int row = t >> 2, q = t & 3;
            ((uint4*)(sB + row * TS + q * 8))[0] = ((const uint4*)g_Wgt)[row * 16 + c * 4 + q];
        }
        __syncthreads();

        #pragma unroll
        for (int kk = 0; kk < 2; kk++) {
            uint32_t fA[2][4];
            #pragma unroll
            for (int mt = 0; mt < 2; mt++) {
                uint32_t off = (uint32_t)(((wm + mt * 16 + a_m) * TS + kk * 16 + a_k) * 2);
                ldmx4(fA[mt], ab + off);
            }
            #pragma unroll
            for (int ntg = 0; ntg < 2; ntg++) {
                uint32_t fB[4];
                uint32_t off = (uint32_t)(((wn + ntg * 16 + b_n) * TS + kk * 16 + b_k) * 2);
                ldmx4(fB, bb + off);
                #pragma unroll
                for (int mt = 0; mt < 2; mt++)
                    #pragma unroll
                    for (int p = 0; p < 2; p++)
                        mma16816(acc[mt][ntg * 2 + p], fA[mt], &fB[p * 2]);
            }
        }
        __syncthreads();
    }

    const int fr = lane >> 2, fc = (lane & 3) * 2;
    #pragma unroll
    for (int mt = 0; mt < 2; mt++)
        #pragma unroll
        for (int nt = 0; nt < 4; nt++) {
            int n = wn + nt * 8 + fc;
            size_t r0 = bm + wm + mt * 16 + fr;
            *(float2*)(g_xw + r0 * GCN_H + n)       = make_float2(acc[mt][nt][0], acc[mt][nt][1]);
            *(float2*)(g_xw + (r0 + 8) * GCN_H + n) = make_float2(acc[mt][nt][2], acc[mt][nt][3]);
        }
}

// ---------------------------------------------------------------------------
// Scatter: adjacency + agg, writes A2 = [gcn | prev_h] fp16
// ---------------------------------------------------------------------------
__global__ __launch_bounds__(128) void scatter_kernel(
    const int* __restrict__ ei, const float* __restrict__ prev_h,
    const float* __restrict__ bg)
{
    __shared__ __align__(16) float xw_s[NUM_AGENTS * GCN_H];
    __shared__ float Adj[NUM_AGENTS * NUM_AGENTS];
    __shared__ float deg_s[NUM_AGENTS], dinv_s[NUM_AGENTS];

    const int env = blockIdx.x;
    const int t   = threadIdx.x;

    if (t < NUM_AGENTS) deg_s[t] = 1.0f;
    #pragma unroll
    for (int i = 0; i < 2; i++) Adj[t + i * 128] = 0.0f;

    #pragma unroll
    for (int i = 0; i < 2; i++)
        ((float4*)xw_s)[t + i * 128] =
            ((const float4*)(g_xw + (size_t)env * NUM_AGENTS * GCN_H))[t + i * 128];

    const int rr = ei[(size_t)env * 256 + t];
    const int cc = ei[(size_t)env * 256 + 128 + t];
    __syncthreads();

    atomicAdd(&deg_s[cc], 1.0f);
    __syncthreads();
    if (t < NUM_AGENTS) dinv_s[t] = rsqrtf(deg_s[t]);
    __syncthreads();

    atomicAdd(&Adj[cc * 16 + rr], dinv_s[rr] * dinv_s[cc]);
    if (t < NUM_AGENTS) atomicAdd(&Adj[t * 16 + t], dinv_s[t] * dinv_s[t]);
    __syncthreads();

    const int j  = t & 63;
    const int cq = t >> 6;
    float xv[NUM_AGENTS];
    #pragma unroll
    for (int r = 0; r < NUM_AGENTS; r++) xv[r] = xw_s[r * GCN_H + j];
    const float bgj = bg[j];

    #pragma unroll
    for (int i = 0; i < 8; i++) {
        int c = cq * 8 + i;
        float s = 0.0f;
        #pragma unroll
        for (int r = 0; r < NUM_AGENTS; r++) s += Adj[c * 16 + r] * xv[r];
        s += bgj;
        size_t node = (size_t)env * NUM_AGENTS + c;
        g_A2[node * 128 + j] = __float2half_rn(s);
    }

    #pragma unroll
    for (int i = 0; i < 2; i++) {
        int f4 = t + i * 128;
        float4 v = ((const float4*)(prev_h + (size_t)env * FLAT_H))[f4];
        int row = f4 >> 4, jj = (f4 & 15) * 4;
        size_t node = (size_t)env * NUM_AGENTS + row;
        __half2* ph = (__half2*)(g_A2 + node * 128 + 64 + jj);
        ph[0] = __floats2half2_rn(v.x, v.y);
        ph[1] = __floats2half2_rn(v.z, v.w);
    }
}

// ---------------------------------------------------------------------------
// GEMM2 (gates + GRU), fp16 single pass, cp.async double buffered.
// BM=128, BN=256, BK=32, 512 thr. Stage = A(10240) + B(20480) = 30720 B.
// ---------------------------------------------------------------------------
#define G2_A    0
#define G2_B    10240
#define G2_STG  30720
#define G2_HS   (2 * G2_STG)                 // 61440: float[128*68] = 34816
#define G2_B2S  (G2_HS + 34816)              // 96256
#define G2_SMEM (G2_B2S + 1024)              // 97280

__global__ __launch_bounds__(512, 1) void gemm_gates(
    const float* __restrict__ prev_h,
    float* __restrict__ h_out)
{
    extern __shared__ __align__(16) char smem[];
    const uint32_t sb = smem_to_u32(smem);
    float* h_s  = (float*)(smem + G2_HS);
    float* b2_s = (float*)(smem + G2_B2S);

    const int t = threadIdx.x, wid = t >> 5, lane = t & 31;
    const size_t bm = (size_t)blockIdx.x * 128;
    const int wm = (wid >> 2) * 32, wn = (wid & 3) * 64;

    const int a_m = (lane & 7) + ((lane >> 3) & 1) * 8;
    const int a_k = ((lane >> 4) & 1) * 8;
    const int b_n = (lane & 7) + ((lane >> 4) & 1) * 8;
    const int b_k = ((lane >> 3) & 1) * 8;

    const int la_row = t >> 2, la_q = t & 3;

    auto issue = [&](int c, int s) {
        uint32_t base = sb + s * G2_STG;
        cp16(base + G2_A + (uint32_t)(la_row * TS + la_q * 8) * 2,
             g_A2 + (bm + la_row) * 128 + c * 32 + la_q * 8);
        #pragma unroll
        for (int i = 0; i < 2; i++) {
            int idx = t + i * 512;
            int row = idx >> 2, q = idx & 3;
            cp16(base + G2_B + (uint32_t)(row * TS + q * 8) * 2,
                 g_B2 + row * 128 + c * 32 + q * 8);
        }
    };

    issue(0, 0);
    CP_COMMIT();

    #pragma unroll
    for (int i = 0; i < 4; i++) {
        int idx = t + i * 512;
        int row = idx >> 4, q = idx & 15;
        float4 v = *(const float4*)(prev_h + (bm + row) * RNN_H + q * 4);
        *(float4*)(h_s + row * 68 + q * 4) = v;
    }
    if (t < 256) b2_s[t] = g_b2[t];

    float acc[2][8][4];
    #pragma unroll
    for (int mt = 0; mt < 2; mt++)
        #pragma unroll
        for (int nt = 0; nt < 8; nt++)
            #pragma unroll
            for (int q = 0; q < 4; q++) acc[mt][nt][q] = 0.0f;

    for (int c = 0; c < 4; c++) {
        if (c + 1 < 4) {
            issue(c + 1, (c + 1) & 1);
            CP_COMMIT();
            CP_WAIT(1);
        } else {
            CP_WAIT(0);
        }
        __syncthreads();

        const uint32_t base = sb + (c & 1) * G2_STG;
        #pragma unroll
        for (int kk = 0; kk < 2; kk++) {
            uint32_t fA[2][4];
            #pragma unroll
            for (int mt = 0; mt < 2; mt++) {
                uint32_t off = (uint32_t)(((wm + mt * 16 + a_m) * TS + kk * 16 + a_k) * 2);
                ldmx4(fA[mt], base + G2_A + off);
            }
            #pragma unroll
            for (int ntg = 0; ntg < 4; ntg++) {
                uint32_t fB[4];
                uint32_t off = (uint32_t)(((wn + ntg * 16 + b_n) * TS + kk * 16 + b_k) * 2);
                ldmx4(fB, base + G2_B + off);
                #pragma unroll
                for (int mt = 0; mt < 2; mt++)
                    #pragma unroll
                    for (int p = 0; p < 2; p++)
                        mma16816(acc[mt][ntg * 2 + p], fA[mt], &fB[p * 2]);
            }
        }
        __syncthreads();
    }

    // ---- fused GRU elementwise ----
    const int fr = lane >> 2, fc = (lane & 3) * 2;
    #pragma unroll
    for (int mt = 0; mt < 2; mt++) {
        #pragma unroll
        for (int nt = 0; nt < 8; nt++) {
            int n = wn + nt * 8 + fc;
            float v0 = acc[mt][nt][0] + b2_s[n];
            float v1 = acc[mt][nt][1] + b2_s[n + 1];
            float v2 = acc[mt][nt][2] + b2_s[n];
            float v3 = acc[mt][nt][3] + b2_s[n + 1];
            float p0 = __shfl_xor_sync(0xFFFFFFFF, v0, 1);
            float p1 = __shfl_xor_sync(0xFFFFFFFF, v1, 1);
            float p2 = __shfl_xor_sync(0xFFFFFFFF, v2, 1);
            float p3 = __shfl_xor_sync(0xFFFFFFFF, v3, 1);
            int j = n >> 2;
            bool is01 = ((n & 2) == 0);
            float rs, zs, nxs, nhs;
            int mrow;
            if (is01) { rs = v0; zs = v1; nxs = p0; nhs = p1; mrow = wm + mt * 16 + fr; }
            else      { rs = p2; zs = p3; nxs = v2; nhs = v3; mrow = wm + mt * 16 + fr + 8; }
            float r = sigf(rs), z = sigf(zs);
            float nn = tanhf(nxs + r * nhs);
            float hp = h_s[mrow * 68 + j];
            h_s[mrow * 68 + j] = (1.0f - z) * nn + z * hp;
        }
    }
    __syncthreads();

    // ---- writeout: h fp32 + fp16 ----
    #pragma unroll
    for (int i = 0; i < 4; i++) {
        int idx = t + i * 512;
        int row = idx >> 4, q = idx & 15;
        float4 v = *(const float4*)(h_s + row * 68 + q * 4);
        *(float4*)(h_out + (bm + row) * RNN_H + q * 4) = v;
    }
    #pragma unroll
    for (int i = 0; i < 2; i++) {
        int idx = t + i * 512;
        int row = idx >> 3, q = idx & 7;
        const float* hp = h_s + row * 68 + q * 8;
        __half hv[8];
        #pragma unroll
        for (int e = 0; e < 8; e++) hv[e] = __float2half_rn(hp[e]);
        *(uint4*)(g_A3 + (bm + row) * RNN_H + q * 8) = *(uint4*)hv;
    }
}

// ---------------------------------------------------------------------------
// GEMM3 — fp16 single pass, cp.async double buffered, 2 CTAs/SM.
// Stage = A(10240) + B(10240) = 20480; x2 = 40960 dynamic.
// ---------------------------------------------------------------------------
#define G3_A   0
#define G3_B   10240
#define G3_STG 20480
#define G3_SMEM (2 * G3_STG)
#define NCHUNK (FLAT_H / 32)

__global__ __launch_bounds__(256, 2) void gemm_mma(
    const float* __restrict__ bias, float* __restrict__ C)
{
    extern __shared__ __align__(16) char smem[];
    const uint32_t sb = smem_to_u32(smem);

    const int t = threadIdx.x, wid = t >> 5, lane = t & 31;
    const int bn = blockIdx.x * 128, bm = blockIdx.y * 128;
    const int wm = (wid >> 2) * 64, wn = (wid & 3) * 32;

    const int a_m = (lane & 7) + ((lane >> 3) & 1) * 8;
    const int a_k = ((lane >> 4) & 1) * 8;
    const int b_n = (lane & 7) + ((lane >> 4) & 1) * 8;
    const int b_k = ((lane >> 3) & 1) * 8;

    auto issue = [&](int c, int s) {
        uint32_t base = sb + s * G3_STG;
        #pragma unroll
        for (int i = 0; i < 2; i++) {
            int idx = t + i * 256;
            int row = idx >> 2, q = idx & 3;
            uint32_t so = (uint32_t)(row * TS + q * 8) * 2;
            cp16(base + G3_A + so, g_A3 + (size_t)(bm + row) * FLAT_H + c * 32 + q * 8);
            cp16(base + G3_B + so, g_B3 + (size_t)(bn + row) * FLAT_H + c * 32 + q * 8);
        }
    };

    float acc[4][4][4];
    #pragma unroll
    for (int mt = 0; mt < 4; mt++)
        #pragma unroll
        for (int ns = 0; ns < 4; ns++)
            #pragma unroll
            for (int q = 0; q < 4; q++) acc[mt][ns][q] = 0.0f;

    issue(0, 0);
    CP_COMMIT();

    for (int c = 0; c < NCHUNK; c++) {
        if (c + 1 < NCHUNK) {
            issue(c + 1, (c + 1) & 1);
            CP_COMMIT();
            CP_WAIT(1);
        } else {
            CP_WAIT(0);
        }
        __syncthreads();

        const uint32_t base = sb + (c & 1) * G3_STG;
        #pragma unroll
        for (int kk = 0; kk < 2; kk++) {
            const int akcol = kk * 16 + a_k;
            const int bkcol = kk * 16 + b_k;
            uint32_t fA[4][4];
            #pragma unroll
            for (int mt = 0; mt < 4; mt++) {
                uint32_t off = (uint32_t)(((wm + mt * 16 + a_m) * TS + akcol) * 2);
                ldmx4(fA[mt], base + G3_A + off);
            }
            uint32_t fB[2][4];
            #pragma unroll
            for (int nt = 0; nt < 2; nt++) {
                uint32_t off = (uint32_t)(((wn + nt * 16 + b_n) * TS + bkcol) * 2);
                ldmx4(fB[nt], base + G3_B + off);
            }
            #pragma unroll
            for (int mt = 0; mt < 4; mt++)
                #pragma unroll
                for (int ns = 0; ns < 4; ns++)
                    mma16816(acc[mt][ns], fA[mt], &fB[ns >> 1][(ns & 1) * 2]);
        }
        __syncthreads();
    }

    const int fr = lane >> 2, fc = (lane & 3) * 2;
    #pragma unroll
    for (int mt = 0; mt < 4; mt++)
        #pragma unroll
        for (int ns = 0; ns < 4; ns++) {
            int col = bn + wn + ns * 8 + fc;
            float2 bv = *(const float2*)(bias + col);
            int r0 = bm + wm + mt * 16 + fr;
            *(float2*)(C + (size_t)r0 * OUT_DIM + col) =
                make_float2(acc[mt][ns][0] + bv.x, acc[mt][ns][1] + bv.y);
            *(float2*)(C + (size_t)(r0 + 8) * OUT_DIM + col) =
                make_float2(acc[mt][ns][2] + bv.x, acc[mt][ns][3] + bv.y);
        }
}

// ---------------------------------------------------------------------------
extern "C" void kernel_launch(void* const* d_in, const int* in_sizes, int n_in,
                              void* d_out, int out_size) {
    const float* x     = (const float*)d_in[0];
    const int*   ei    = (const int*)  d_in[1];
    const float* ph    = (const float*)d_in[2];
    const float* Wg    = (const float*)d_in[3];
    const float* bg    = (const float*)d_in[4];
    const float* W_ih  = (const float*)d_in[5];
    const float* W_hh  = (const float*)d_in[6];
    const float* b_ih  = (const float*)d_in[7];
    const float* b_hh  = (const float*)d_in[8];
    const float* W_lin = (const float*)d_in[9];
    const float* b_lin = (const float*)d_in[10];

    float* out = (float*)d_out;
    bool has_nh = (out_size >= NUM_ENVS * (OUT_DIM + FLAT_H));
    float* hdst;
    if (has_nh) {
        hdst = out + (size_t)NUM_ENVS * OUT_DIM;
    } else {
        cudaGetSymbolAddress((void**)&hdst, g_hbuf);
    }

    static bool init = false;
    if (!init) {
        cudaFuncSetAttribute(gemm_gates, cudaFuncAttributeMaxDynamicSharedMemorySize,
                             G2_SMEM);
        cudaFuncSetAttribute(gemm_mma, cudaFuncAttributeMaxDynamicSharedMemorySize,
                             G3_SMEM);
        init = true;
    }

    pack_w_kernel<<<(PK_TOT + 255) / 256, 256>>>(Wg, W_ih, W_hh, b_ih, b_hh, W_lin);
    gemm_xw<<<NNODE / 128, 256>>>(x);
    scatter_kernel<<<NUM_ENVS, 128>>>(ei, ph, bg);
    gemm_gates<<<NNODE / 128, 512, G2_SMEM>>>(ph, hdst);
    gemm_mma<<<dim3(OUT_DIM / 128, NUM_ENVS / 128), 256, G3_SMEM>>>(b_lin, out);
}

// round 10
// speedup vs baseline: 3.9218x; 1.0560x over previous
#include <cuda_runtime.h>
#include <cuda_fp16.h>
#include <math.h>
#include <cstdint>

#define NUM_ENVS 16384
#define NUM_AGENTS 16
#define IN_DIM 128
#define GCN_H 64
#define RNN_H 64
#define OUT_DIM 512
#define FLAT_H (NUM_AGENTS * RNN_H)      // 1024
#define NNODE ((size_t)NUM_ENVS * NUM_AGENTS)   // 262144

// ---------------- static device scratch -------------------------------------
__device__ float  g_hbuf[(size_t)NUM_ENVS * FLAT_H];
__device__ __align__(16) __half g_A2[NNODE * 128];        // [gcn | prev_h] fp16
__device__ __align__(16) __half g_A3[NNODE * RNN_H];      // h_new fp16
__device__ __align__(16) __half g_Wgt[GCN_H * IN_DIM];    // Wgcn^T fp16
__device__ __align__(16) __half g_B2[256 * 128];          // gate weights fp16
__device__ float g_b2[256];
__device__ __align__(16) __half g_B3[(size_t)OUT_DIM * FLAT_H];

// ---------------- helpers ---------------------------------------------------
__device__ __forceinline__ uint32_t smem_to_u32(const void* p) {
    uint32_t a;
    asm("{ .reg .u64 t; cvta.to.shared.u64 t, %1; cvt.u32.u64 %0, t; }" : "=r"(a) : "l"(p));
    return a;
}
__device__ __forceinline__ float sigf(float v) { return 1.0f / (1.0f + expf(-v)); }

__device__ __forceinline__ void ldmx4(uint32_t* r, uint32_t addr) {
    asm volatile("ldmatrix.sync.aligned.m8n8.x4.shared.b16 {%0,%1,%2,%3}, [%4];"
                 : "=r"(r[0]), "=r"(r[1]), "=r"(r[2]), "=r"(r[3]) : "r"(addr));
}
__device__ __forceinline__ void mma16816(float* d, const uint32_t* a, const uint32_t* b) {
    asm volatile("mma.sync.aligned.m16n8k16.row.col.f32.f16.f16.f32 "
                 "{%0,%1,%2,%3}, {%4,%5,%6,%7}, {%8,%9}, {%0,%1,%2,%3};"
                 : "+f"(d[0]), "+f"(d[1]), "+f"(d[2]), "+f"(d[3])
                 : "r"(a[0]), "r"(a[1]), "r"(a[2]), "r"(a[3]), "r"(b[0]), "r"(b[1]));
}
__device__ __forceinline__ void cp16(uint32_t dst, const void* src) {
    asm volatile("cp.async.cg.shared.global [%0], [%1], 16;" :: "r"(dst), "l"(src));
}
#define CP_COMMIT() asm volatile("cp.async.commit_group;")
#define CP_WAIT(N)  asm volatile("cp.async.wait_group %0;" :: "n"(N))

// ---------------------------------------------------------------------------
// pack weights (fp16)
// ---------------------------------------------------------------------------
#define PK_WGT (GCN_H * IN_DIM)
#define PK_B2  (256 * 128)
#define PK_WL  (OUT_DIM * FLAT_H)
#define PK_TOT (PK_WGT + PK_B2 + 256 + PK_WL)

__global__ void pack_w_kernel(const float* __restrict__ Wg,
                              const float* __restrict__ W_ih,
                              const float* __restrict__ W_hh,
                              const float* __restrict__ b_ih,
                              const float* __restrict__ b_hh,
                              const float* __restrict__ Wl) {
    int idx = blockIdx.x * 256 + threadIdx.x;
    if (idx < PK_WGT) {
        int n = idx >> 7, k = idx & 127;
        g_Wgt[idx] = __float2half_rn(Wg[k * GCN_H + n]);
    } else if (idx < PK_WGT + PK_B2) {
        int r = idx - PK_WGT;
        int n = r >> 7, k = r & 127;
        int j = n >> 2, g = n & 3;
        float w = 0.0f;
        if (g == 0)      w = (k < 64) ? W_ih[j * 64 + k]         : W_hh[j * 64 + (k - 64)];
        else if (g == 1) w = (k < 64) ? W_ih[(64 + j) * 64 + k]  : W_hh[(64 + j) * 64 + (k - 64)];
        else if (g == 2) w = (k < 64) ? W_ih[(128 + j) * 64 + k] : 0.0f;
        else             w = (k < 64) ? 0.0f                     : W_hh[(128 + j) * 64 + (k - 64)];
        g_B2[r] = __float2half_rn(w);
    } else if (idx < PK_WGT + PK_B2 + 256) {
        int n = idx - PK_WGT - PK_B2;
        int j = n >> 2, g = n & 3;
        float b;
        if (g == 0)      b = b_ih[j] + b_hh[j];
        else if (g == 1) b = b_ih[64 + j] + b_hh[64 + j];
        else if (g == 2) b = b_ih[128 + j];
        else             b = b_hh[128 + j];
        g_b2[n] = b;
    } else if (idx < PK_TOT) {
        int r = idx - PK_WGT - PK_B2 - 256;
        g_B3[r] = __float2half_rn(Wl[r]);
    }
}

// ---------------------------------------------------------------------------
// gcn_front: xw = x @ Wgcn (fp16 MMA) + per-env adjacency + agg, emits A2.
// 1 block = 128 rows = 8 envs. 256 threads.
// ---------------------------------------------------------------------------
#define TS 40
// dynamic smem layout (bytes)
#define F_SA   0
#define F_SB   10240                     // sA: 128*40*2
#define F_XW   15360                     // sB: 64*40*2 = 5120
#define F_ADJ  (F_XW + 128 * 68 * 4)    // xw: 34816 -> 50176
#define F_DEG  (F_ADJ + 8 * 256 * 4)    // adj: 8192 -> 58368
#define F_DNV  (F_DEG + 512)            // 58880
#define F_SMEM (F_DNV + 512)            // 59392

__global__ __launch_bounds__(256, 2) void gcn_front(
    const float* __restrict__ x, const int* __restrict__ ei,
    const float* __restrict__ prev_h, const float* __restrict__ bg)
{
    extern __shared__ __align__(16) char smem[];
    __half* sA   = (__half*)(smem + F_SA);
    __half* sB   = (__half*)(smem + F_SB);
    float*  xw_s = (float*)(smem + F_XW);     // stride 68
    float*  Adj  = (float*)(smem + F_ADJ);    // [8][256]
    float*  deg  = (float*)(smem + F_DEG);    // [8][16]
    float*  dnv  = (float*)(smem + F_DNV);

    const int t = threadIdx.x, wid = t >> 5, lane = t & 31;
    const size_t bm = (size_t)blockIdx.x * 128;
    const int e0 = blockIdx.x * 8;            // first env of this block
    const int wm = (wid >> 1) * 32, wn = (wid & 1) * 32;
    const uint32_t ab = smem_to_u32(sA), bb = smem_to_u32(sB);

    const int a_m = (lane & 7) + ((lane >> 3) & 1) * 8;
    const int a_k = ((lane >> 4) & 1) * 8;
    const int b_n = (lane & 7) + ((lane >> 4) & 1) * 8;
    const int b_k = ((lane >> 3) & 1) * 8;

    // zero Adj/deg while MMA smem is idle
    #pragma unroll
    for (int i = 0; i < 8; i++) Adj[t + i * 256] = 0.0f;
    if (t < 128) deg[t] = 1.0f;

    float acc[2][4][4];
    #pragma unroll
    for (int mt = 0; mt < 2; mt++)
        #pragma unroll
        for (int nt = 0; nt < 4; nt++)
            #pragma unroll
            for (int q = 0; q < 4; q++) acc[mt][nt][q] = 0.0f;

    for (int c = 0; c < 4; c++) {
        #pragma unroll
        for (int i = 0; i < 4; i++) {
            int idx = t + i * 256;
            int row = idx >> 3, q = idx & 7;
            float4 v = *(const float4*)(x + (bm + row) * IN_DIM + c * 32 + q * 4);
            __half2* ph = (__half2*)(sA + row * TS + q * 4);
            ph[0] = __floats2half2_rn(v.x, v.y);
            ph[1] = __floats2half2_rn(v.z, v.w);
        }
        {
            int row = t >> 2, q = t & 3;
            ((uint4*)(sB + row * TS + q * 8))[0] = ((const uint4*)g_Wgt)[row * 16 + c * 4 + q];
        }
        __syncthreads();

        #pragma unroll
        for (int kk = 0; kk < 2; kk++) {
            uint32_t fA[2][4];
            #pragma unroll
            for (int mt = 0; mt < 2; mt++) {
                uint32_t off = (uint32_t)(((wm + mt * 16 + a_m) * TS + kk * 16 + a_k) * 2);
                ldmx4(fA[mt], ab + off);
            }
            #pragma unroll
            for (int ntg = 0; ntg < 2; ntg++) {
                uint32_t fB[4];
                uint32_t off = (uint32_t)(((wn + ntg * 16 + b_n) * TS + kk * 16 + b_k) * 2);
                ldmx4(fB, bb + off);
                #pragma unroll
                for (int mt = 0; mt < 2; mt++)
                    #pragma unroll
                    for (int p = 0; p < 2; p++)
                        mma16816(acc[mt][ntg * 2 + p], fA[mt], &fB[p * 2]);
            }
        }
        __syncthreads();
    }

    // ---- xw fragments -> smem ----
    const int fr = lane >> 2, fc = (lane & 3) * 2;
    #pragma unroll
    for (int mt = 0; mt < 2; mt++)
        #pragma unroll
        for (int nt = 0; nt < 4; nt++) {
            int col = wn + nt * 8 + fc;
            int r0 = wm + mt * 16 + fr;
            *(float2*)(xw_s + r0 * 68 + col)       = make_float2(acc[mt][nt][0], acc[mt][nt][1]);
            *(float2*)(xw_s + (r0 + 8) * 68 + col) = make_float2(acc[mt][nt][2], acc[mt][nt][3]);
        }

    // ---- edges: degree ----
    int rr_[4], cc_[4];
    #pragma unroll
    for (int i = 0; i < 4; i++) {
        int eidx = t + i * 256;                // 0..1023
        int el = eidx >> 7, e = eidx & 127;    // env_local, edge
        rr_[i] = ei[(size_t)(e0 + el) * 256 + e];
        cc_[i] = ei[(size_t)(e0 + el) * 256 + 128 + e];
    }
    __syncthreads();
    #pragma unroll
    for (int i = 0; i < 4; i++) {
        int el = (t + i * 256) >> 7;
        atomicAdd(&deg[el * 16 + cc_[i]], 1.0f);
    }
    __syncthreads();
    if (t < 128) dnv[t] = rsqrtf(deg[t]);
    __syncthreads();

    // ---- adjacency build ----
    #pragma unroll
    for (int i = 0; i < 4; i++) {
        int el = (t + i * 256) >> 7;
        atomicAdd(&Adj[el * 256 + cc_[i] * 16 + rr_[i]],
                  dnv[el * 16 + rr_[i]] * dnv[el * 16 + cc_[i]]);
    }
    if (t < 128) {
        int el = t >> 4, r = t & 15;
        float d = dnv[t];
        atomicAdd(&Adj[el * 256 + r * 17], d * d);
    }
    __syncthreads();

    // ---- agg = Adj @ xw + bias -> A2 cols [0,64) ----
    {
        const int j  = t & 63;
        const int cg = t >> 6;                 // 0..3 -> c groups of 4
        const float bgj = bg[j];
        #pragma unroll
        for (int el = 0; el < 8; el++) {
            float xv[NUM_AGENTS];
            #pragma unroll
            for (int r = 0; r < NUM_AGENTS; r++)
                xv[r] = xw_s[(el * 16 + r) * 68 + j];
            #pragma unroll
            for (int i = 0; i < 4; i++) {
                int c = cg * 4 + i;
                float s = 0.0f;
                const float* arow = Adj + el * 256 + c * 16;
                #pragma unroll
                for (int r = 0; r < NUM_AGENTS; r++) s += arow[r] * xv[r];
                s += bgj;
                size_t node = (size_t)(e0 + el) * 16 + c;
                g_A2[node * 128 + j] = __float2half_rn(s);
            }
        }
    }

    // ---- prev_h -> A2 cols [64,128) ----
    #pragma unroll
    for (int i = 0; i < 8; i++) {
        int idx = t + i * 256;                 // 0..2047 float4
        int el = idx >> 8, f4 = idx & 255;
        float4 v = ((const float4*)(prev_h + (size_t)(e0 + el) * FLAT_H))[f4];
        int row = f4 >> 4, jj = (f4 & 15) * 4;
        size_t node = (size_t)(e0 + el) * 16 + row;
        __half2* ph = (__half2*)(g_A2 + node * 128 + 64 + jj);
        ph[0] = __floats2half2_rn(v.x, v.y);
        ph[1] = __floats2half2_rn(v.z, v.w);
    }
}

// ---------------------------------------------------------------------------
// GEMM2 (gates + GRU): BM=128, BN=128 (N-split over 2 CTAs), BK=32, 256 thr,
// 2 CTAs/SM. 8 warps (2M x 4N), warp tile 64x32. cp.async double buffered.
// ---------------------------------------------------------------------------
#define G2_A    0
#define G2_B    10240
#define G2_STG  20480
#define G2_HS   (2 * G2_STG)                 // 40960: float[128*36] = 18432
#define G2_B2S  (G2_HS + 18432)              // 59392: float[128]
#define G2_SMEM (G2_B2S + 512)               // 59904

__global__ __launch_bounds__(256, 2) void gemm_gates(
    const float* __restrict__ prev_h,
    float* __restrict__ h_out)
{
    extern __shared__ __align__(16) char smem[];
    const uint32_t sb = smem_to_u32(smem);
    float* h_s  = (float*)(smem + G2_HS);     // stride 36
    float* b2_s = (float*)(smem + G2_B2S);

    const int t = threadIdx.x, wid = t >> 5, lane = t & 31;
    const int bn = blockIdx.x;                // 0..1 (j-half)
    const size_t bm = (size_t)blockIdx.y * 128;
    const int j0 = bn * 32;
    const int wm = (wid >> 2) * 64, wn = (wid & 3) * 32;

    const int a_m = (lane & 7) + ((lane >> 3) & 1) * 8;
    const int a_k = ((lane >> 4) & 1) * 8;
    const int b_n = (lane & 7) + ((lane >> 4) & 1) * 8;
    const int b_k = ((lane >> 3) & 1) * 8;

    auto issue = [&](int c, int s) {
        uint32_t base = sb + s * G2_STG;
        #pragma unroll
        for (int i = 0; i < 2; i++) {
            int idx = t + i * 256;
            int row = idx >> 2, q = idx & 3;
            uint32_t so = (uint32_t)(row * TS + q * 8) * 2;
            cp16(base + G2_A + so, g_A2 + (bm + row) * 128 + c * 32 + q * 8);
            cp16(base + G2_B + so, g_B2 + (size_t)(bn * 128 + row) * 128 + c * 32 + q * 8);
        }
    };

    issue(0, 0);
    CP_COMMIT();

    // preload prev_h slice + biases
    #pragma unroll
    for (int i = 0; i < 4; i++) {
        int idx = t + i * 256;                // 0..1023 float4
        int row = idx >> 3, q = idx & 7;
        float4 v = *(const float4*)(prev_h + (bm + row) * RNN_H + j0 + q * 4);
        *(float4*)(h_s + row * 36 + q * 4) = v;
    }
    if (t < 128) b2_s[t] = g_b2[bn * 128 + t];

    float acc[4][4][4];
    #pragma unroll
    for (int mt = 0; mt < 4; mt++)
        #pragma unroll
        for (int ns = 0; ns < 4; ns++)
            #pragma unroll
            for (int q = 0; q < 4; q++) acc[mt][ns][q] = 0.0f;

    for (int c = 0; c < 4; c++) {
        if (c + 1 < 4) {
            issue(c + 1, (c + 1) & 1);
            CP_COMMIT();
            CP_WAIT(1);
        } else {
            CP_WAIT(0);
        }
        __syncthreads();

        const uint32_t base = sb + (c & 1) * G2_STG;
        #pragma unroll
        for (int kk = 0; kk < 2; kk++) {
            uint32_t fA[4][4];
            #pragma unroll
            for (int mt = 0; mt < 4; mt++) {
                uint32_t off = (uint32_t)(((wm + mt * 16 + a_m) * TS + kk * 16 + a_k) * 2);
                ldmx4(fA[mt], base + G2_A + off);
            }
            uint32_t fB[2][4];
            #pragma unroll
            for (int nt = 0; nt < 2; nt++) {
                uint32_t off = (uint32_t)(((wn + nt * 16 + b_n) * TS + kk * 16 + b_k) * 2);
                ldmx4(fB[nt], base + G2_B + off);
            }
            #pragma unroll
            for (int mt = 0; mt < 4; mt++)
                #pragma unroll
                for (int ns = 0; ns < 4; ns++)
                    mma16816(acc[mt][ns], fA[mt], &fB[ns >> 1][(ns & 1) * 2]);
        }
        __syncthreads();
    }

    // ---- fused GRU elementwise ----
    const int fr = lane >> 2, fc = (lane & 3) * 2;
    #pragma unroll
    for (int mt = 0; mt < 4; mt++) {
        #pragma unroll
        for (int ns = 0; ns < 4; ns++) {
            int n = wn + ns * 8 + fc;         // local col 0..127
            float v0 = acc[mt][ns][0] + b2_s[n];
            float v1 = acc[mt][ns][1] + b2_s[n + 1];
            float v2 = acc[mt][ns][2] + b2_s[n];
            float v3 = acc[mt][ns][3] + b2_s[n + 1];
            float p0 = __shfl_xor_sync(0xFFFFFFFF, v0, 1);
            float p1 = __shfl_xor_sync(0xFFFFFFFF, v1, 1);
            float p2 = __shfl_xor_sync(0xFFFFFFFF, v2, 1);
            float p3 = __shfl_xor_sync(0xFFFFFFFF, v3, 1);
            int jl = n >> 2;                  // local j 0..31
            bool is01 = ((n & 2) == 0);
            float rs, zs, nxs, nhs;
            int mrow;
            if (is01) { rs = v0; zs = v1; nxs = p0; nhs = p1; mrow = wm + mt * 16 + fr; }
            else      { rs = p2; zs = p3; nxs = v2; nhs = v3; mrow = wm + mt * 16 + fr + 8; }
            float r = sigf(rs), z = sigf(zs);
            float nn = tanhf(nxs + r * nhs);
            float hp = h_s[mrow * 36 + jl];
            h_s[mrow * 36 + jl] = (1.0f - z) * nn + z * hp;
        }
    }
    __syncthreads();

    // ---- writeout: h fp32 slice + fp16 slice ----
    #pragma unroll
    for (int i = 0; i < 4; i++) {
        int idx = t + i * 256;
        int row = idx >> 3, q = idx & 7;
        float4 v = *(const float4*)(h_s + row * 36 + q * 4);
        *(float4*)(h_out + (bm + row) * RNN_H + j0 + q * 4) = v;
    }
    #pragma unroll
    for (int i = 0; i < 2; i++) {
        int idx = t + i * 256;                // 0..511
        int row = idx >> 2, q = idx & 3;
        const float* hp = h_s + row * 36 + q * 8;
        __half hv[8];
        #pragma unroll
        for (int e = 0; e < 8; e++) hv[e] = __float2half_rn(hp[e]);
        *(uint4*)(g_A3 + (bm + row) * RNN_H + j0 + q * 8) = *(uint4*)hv;
    }
}

// ---------------------------------------------------------------------------
// GEMM3 — unchanged from R9 (proven): fp16, double buffered, 2 CTAs/SM.
// ---------------------------------------------------------------------------
#define G3_A   0
#define G3_B   10240
#define G3_STG 20480
#define G3_SMEM (2 * G3_STG)
#define NCHUNK (FLAT_H / 32)

__global__ __launch_bounds__(256, 2) void gemm_mma(
    const float* __restrict__ bias, float* __restrict__ C)
{
    extern __shared__ __align__(16) char smem[];
    const uint32_t sb = smem_to_u32(smem);

    const int t = threadIdx.x, wid = t >> 5, lane = t & 31;
    const int bn = blockIdx.x * 128, bm = blockIdx.y * 128;
    const int wm = (wid >> 2) * 64, wn = (wid & 3) * 32;

    const int a_m = (lane & 7) + ((lane >> 3) & 1) * 8;
    const int a_k = ((lane >> 4) & 1) * 8;
    const int b_n = (lane & 7) + ((lane >> 4) & 1) * 8;
    const int b_k = ((lane >> 3) & 1) * 8;

    auto issue = [&](int c, int s) {
        uint32_t base = sb + s * G3_STG;
        #pragma unroll
        for (int i = 0; i < 2; i++) {
            int idx = t + i * 256;
            int row = idx >> 2, q = idx & 3;
            uint32_t so = (uint32_t)(row * TS + q * 8) * 2;
            cp16(base + G3_A + so, g_A3 + (size_t)(bm + row) * FLAT_H + c * 32 + q * 8);
            cp16(base + G3_B + so, g_B3 + (size_t)(bn + row) * FLAT_H + c * 32 + q * 8);
        }
    };

    float acc[4][4][4];
    #pragma unroll
    for (int mt = 0; mt < 4; mt++)
        #pragma unroll
        for (int ns = 0; ns < 4; ns++)
            #pragma unroll
            for (int q = 0; q < 4; q++) acc[mt][ns][q] = 0.0f;

    issue(0, 0);
    CP_COMMIT();

    for (int c = 0; c < NCHUNK; c++) {
        if (c + 1 < NCHUNK) {
            issue(c + 1, (c + 1) & 1);
            CP_COMMIT();
            CP_WAIT(1);
        } else {
            CP_WAIT(0);
        }
        __syncthreads();

        const uint32_t base = sb + (c & 1) * G3_STG;
        #pragma unroll
        for (int kk = 0; kk < 2; kk++) {
            const int akcol = kk * 16 + a_k;
            const int bkcol = kk * 16 + b_k;
            uint32_t fA[4][4];
            #pragma unroll
            for (int mt = 0; mt < 4; mt++) {
                uint32_t off = (uint32_t)(((wm + mt * 16 + a_m) * TS + akcol) * 2);
                ldmx4(fA[mt], base + G3_A + off);
            }
            uint32_t fB[2][4];
            #pragma unroll
            for (int nt = 0; nt < 2; nt++) {
                uint32_t off = (uint32_t)(((wn + nt * 16 + b_n) * TS + bkcol) * 2);
                ldmx4(fB[nt], base + G3_B + off);
            }
            #pragma unroll
            for (int mt = 0; mt < 4; mt++)
                #pragma unroll
                for (int ns = 0; ns < 4; ns++)
                    mma16816(acc[mt][ns], fA[mt], &fB[ns >> 1][(ns & 1) * 2]);
        }
        __syncthreads();
    }

    const int fr = lane >> 2, fc = (lane & 3) * 2;
    #pragma unroll
    for (int mt = 0; mt < 4; mt++)
        #pragma unroll
        for (int ns = 0; ns < 4; ns++) {
            int col = bn + wn + ns * 8 + fc;
            float2 bv = *(const float2*)(bias + col);
            int r0 = bm + wm + mt * 16 + fr;
            *(float2*)(C + (size_t)r0 * OUT_DIM + col) =
                make_float2(acc[mt][ns][0] + bv.x, acc[mt][ns][1] + bv.y);
            *(float2*)(C + (size_t)(r0 + 8) * OUT_DIM + col) =
                make_float2(acc[mt][ns][2] + bv.x, acc[mt][ns][3] + bv.y);
        }
}

// ---------------------------------------------------------------------------
extern "C" void kernel_launch(void* const* d_in, const int* in_sizes, int n_in,
                              void* d_out, int out_size) {
    const float* x     = (const float*)d_in[0];
    const int*   ei    = (const int*)  d_in[1];
    const float* ph    = (const float*)d_in[2];
    const float* Wg    = (const float*)d_in[3];
    const float* bg    = (const float*)d_in[4];
    const float* W_ih  = (const float*)d_in[5];
    const float* W_hh  = (const float*)d_in[6];
    const float* b_ih  = (const float*)d_in[7];
    const float* b_hh  = (const float*)d_in[8];
    const float* W_lin = (const float*)d_in[9];
    const float* b_lin = (const float*)d_in[10];

    float* out = (float*)d_out;
    bool has_nh = (out_size >= NUM_ENVS * (OUT_DIM + FLAT_H));
    float* hdst;
    if (has_nh) {
        hdst = out + (size_t)NUM_ENVS * OUT_DIM;
    } else {
        cudaGetSymbolAddress((void**)&hdst, g_hbuf);
    }

    static bool init = false;
    if (!init) {
        cudaFuncSetAttribute(gcn_front, cudaFuncAttributeMaxDynamicSharedMemorySize,
                             F_SMEM);
        cudaFuncSetAttribute(gemm_gates, cudaFuncAttributeMaxDynamicSharedMemorySize,
                             G2_SMEM);
        cudaFuncSetAttribute(gemm_mma, cudaFuncAttributeMaxDynamicSharedMemorySize,
                             G3_SMEM);
        init = true;
    }

    pack_w_kernel<<<(PK_TOT + 255) / 256, 256>>>(Wg, W_ih, W_hh, b_ih, b_hh, W_lin);
    gcn_front<<<NNODE / 128, 256, F_SMEM>>>(x, ei, ph, bg);
    gemm_gates<<<dim3(2, NNODE / 128), 256, G2_SMEM>>>(ph, hdst);
    gemm_mma<<<dim3(OUT_DIM / 128, NUM_ENVS / 128), 256, G3_SMEM>>>(b_lin, out);
}

// round 11
// speedup vs baseline: 4.0309x; 1.0278x over previous
#include <cuda_runtime.h>
#include <cuda_fp16.h>
#include <math.h>
#include <cstdint>

#define NUM_ENVS 16384
#define NUM_AGENTS 16
#define IN_DIM 128
#define GCN_H 64
#define RNN_H 64
#define OUT_DIM 512
#define FLAT_H (NUM_AGENTS * RNN_H)      // 1024
#define NNODE ((size_t)NUM_ENVS * NUM_AGENTS)   // 262144

// ---------------- static device scratch -------------------------------------
__device__ float  g_hbuf[(size_t)NUM_ENVS * FLAT_H];
__device__ __align__(16) __half g_A2[NNODE * 128];        // [gcn | prev_h] fp16
__device__ __align__(16) __half g_A3[NNODE * RNN_H];      // h_new fp16
__device__ __align__(16) __half g_Wgt[GCN_H * IN_DIM];    // Wgcn^T fp16
__device__ __align__(16) __half g_B2[256 * 128];          // gate weights fp16
__device__ float g_b2[256];
__device__ __align__(16) __half g_B3[(size_t)OUT_DIM * FLAT_H];

// ---------------- helpers ---------------------------------------------------
__device__ __forceinline__ uint32_t smem_to_u32(const void* p) {
    uint32_t a;
    asm("{ .reg .u64 t; cvta.to.shared.u64 t, %1; cvt.u32.u64 %0, t; }" : "=r"(a) : "l"(p));
    return a;
}
__device__ __forceinline__ float sigf(float v) { return 1.0f / (1.0f + expf(-v)); }

__device__ __forceinline__ void ldmx4(uint32_t* r, uint32_t addr) {
    asm volatile("ldmatrix.sync.aligned.m8n8.x4.shared.b16 {%0,%1,%2,%3}, [%4];"
                 : "=r"(r[0]), "=r"(r[1]), "=r"(r[2]), "=r"(r[3]) : "r"(addr));
}
__device__ __forceinline__ void mma16816(float* d, const uint32_t* a, const uint32_t* b) {
    asm volatile("mma.sync.aligned.m16n8k16.row.col.f32.f16.f16.f32 "
                 "{%0,%1,%2,%3}, {%4,%5,%6,%7}, {%8,%9}, {%0,%1,%2,%3};"
                 : "+f"(d[0]), "+f"(d[1]), "+f"(d[2]), "+f"(d[3])
                 : "r"(a[0]), "r"(a[1]), "r"(a[2]), "r"(a[3]), "r"(b[0]), "r"(b[1]));
}
__device__ __forceinline__ void cp16(uint32_t dst, const void* src) {
    asm volatile("cp.async.cg.shared.global [%0], [%1], 16;" :: "r"(dst), "l"(src));
}
#define CP_COMMIT() asm volatile("cp.async.commit_group;")
#define CP_WAIT(N)  asm volatile("cp.async.wait_group %0;" :: "n"(N))

// ---------------------------------------------------------------------------
// pack weights (fp16)
// ---------------------------------------------------------------------------
#define PK_WGT (GCN_H * IN_DIM)
#define PK_B2  (256 * 128)
#define PK_WL  (OUT_DIM * FLAT_H)
#define PK_TOT (PK_WGT + PK_B2 + 256 + PK_WL)

__global__ void pack_w_kernel(const float* __restrict__ Wg,
                              const float* __restrict__ W_ih,
                              const float* __restrict__ W_hh,
                              const float* __restrict__ b_ih,
                              const float* __restrict__ b_hh,
                              const float* __restrict__ Wl) {
    int idx = blockIdx.x * 256 + threadIdx.x;
    if (idx < PK_WGT) {
        int n = idx >> 7, k = idx & 127;
        g_Wgt[idx] = __float2half_rn(Wg[k * GCN_H + n]);
    } else if (idx < PK_WGT + PK_B2) {
        int r = idx - PK_WGT;
        int n = r >> 7, k = r & 127;
        int j = n >> 2, g = n & 3;
        float w = 0.0f;
        if (g == 0)      w = (k < 64) ? W_ih[j * 64 + k]         : W_hh[j * 64 + (k - 64)];
        else if (g == 1) w = (k < 64) ? W_ih[(64 + j) * 64 + k]  : W_hh[(64 + j) * 64 + (k - 64)];
        else if (g == 2) w = (k < 64) ? W_ih[(128 + j) * 64 + k] : 0.0f;
        else             w = (k < 64) ? 0.0f                     : W_hh[(128 + j) * 64 + (k - 64)];
        g_B2[r] = __float2half_rn(w);
    } else if (idx < PK_WGT + PK_B2 + 256) {
        int n = idx - PK_WGT - PK_B2;
        int j = n >> 2, g = n & 3;
        float b;
        if (g == 0)      b = b_ih[j] + b_hh[j];
        else if (g == 1) b = b_ih[64 + j] + b_hh[64 + j];
        else if (g == 2) b = b_ih[128 + j];
        else             b = b_hh[128 + j];
        g_b2[n] = b;
    } else if (idx < PK_TOT) {
        int r = idx - PK_WGT - PK_B2 - 256;
        g_B3[r] = __float2half_rn(Wl[r]);
    }
}

// ---------------------------------------------------------------------------
// gcn_front: xw = x @ Wgcn (fp16 MMA) + per-env adjacency + agg, emits A2.
// 1 block = 128 rows = 8 envs. 256 threads, 2 CTAs/SM.
// B preloaded once (cp.async); A chunk register-prefetched.
// ---------------------------------------------------------------------------
#define TS 40
// dynamic smem layout (bytes)
#define F_SB4  0                          // 4 chunks x 64*TS*2 = 20480
#define F_SA   20480                      // 128*TS*2 = 10240
#define F_XW   30720                      // float[128*68] = 34816
#define F_ADJ  65536                      // float[8*256] = 8192
#define F_DEG  73728                      // 512
#define F_DNV  74240                      // 512
#define F_SMEM 74752

__global__ __launch_bounds__(256, 2) void gcn_front(
    const float* __restrict__ x, const int* __restrict__ ei,
    const float* __restrict__ prev_h, const float* __restrict__ bg)
{
    extern __shared__ __align__(16) char smem[];
    __half* sA   = (__half*)(smem + F_SA);
    float*  xw_s = (float*)(smem + F_XW);     // stride 68
    float*  Adj  = (float*)(smem + F_ADJ);    // [8][256]
    float*  deg  = (float*)(smem + F_DEG);    // [8][16]
    float*  dnv  = (float*)(smem + F_DNV);

    const int t = threadIdx.x, wid = t >> 5, lane = t & 31;
    const size_t bm = (size_t)blockIdx.x * 128;
    const int e0 = blockIdx.x * 8;
    const int wm = (wid >> 1) * 32, wn = (wid & 1) * 32;
    const uint32_t sb = smem_to_u32(smem);
    const uint32_t ab = sb + F_SA;

    const int a_m = (lane & 7) + ((lane >> 3) & 1) * 8;
    const int a_k = ((lane >> 4) & 1) * 8;
    const int b_n = (lane & 7) + ((lane >> 4) & 1) * 8;
    const int b_k = ((lane >> 3) & 1) * 8;

    // ---- preload ALL of B (4 chunks) via cp.async ----
    {
        int row = t >> 2, q = t & 3;
        #pragma unroll
        for (int c = 0; c < 4; c++)
            cp16(sb + F_SB4 + (uint32_t)c * 5120 + (uint32_t)(row * TS + q * 8) * 2,
                 g_Wgt + row * 128 + c * 32 + q * 8);
        CP_COMMIT();
    }

    // zero Adj/deg while loads fly
    #pragma unroll
    for (int i = 0; i < 8; i++) Adj[t + i * 256] = 0.0f;
    if (t < 128) deg[t] = 1.0f;

    // ---- A chunk register prefetch ----
    float4 pax[4];
    auto lda = [&](int c) {
        #pragma unroll
        for (int i = 0; i < 4; i++) {
            int idx = t + i * 256;
            int row = idx >> 3, q = idx & 7;
            pax[i] = *(const float4*)(x + (bm + row) * IN_DIM + c * 32 + q * 4);
        }
    };
    auto stsa = [&]() {
        #pragma unroll
        for (int i = 0; i < 4; i++) {
            int idx = t + i * 256;
            int row = idx >> 3, q = idx & 7;
            __half2* ph = (__half2*)(sA + row * TS + q * 4);
            ph[0] = __floats2half2_rn(pax[i].x, pax[i].y);
            ph[1] = __floats2half2_rn(pax[i].z, pax[i].w);
        }
    };

    float acc[2][4][4];
    #pragma unroll
    for (int mt = 0; mt < 2; mt++)
        #pragma unroll
        for (int nt = 0; nt < 4; nt++)
            #pragma unroll
            for (int q = 0; q < 4; q++) acc[mt][nt][q] = 0.0f;

    lda(0);
    stsa();
    CP_WAIT(0);
    __syncthreads();

    for (int c = 0; c < 4; c++) {
        if (c < 3) lda(c + 1);                      // overlap LDG with MMA

        const uint32_t bbc = sb + F_SB4 + (uint32_t)c * 5120;
        #pragma unroll
        for (int kk = 0; kk < 2; kk++) {
            uint32_t fA[2][4];
            #pragma unroll
            for (int mt = 0; mt < 2; mt++) {
                uint32_t off = (uint32_t)(((wm + mt * 16 + a_m) * TS + kk * 16 + a_k) * 2);
                ldmx4(fA[mt], ab + off);
            }
            #pragma unroll
            for (int ntg = 0; ntg < 2; ntg++) {
                uint32_t fB[4];
                uint32_t off = (uint32_t)(((wn + ntg * 16 + b_n) * TS + kk * 16 + b_k) * 2);
                ldmx4(fB, bbc + off);
                #pragma unroll
                for (int mt = 0; mt < 2; mt++)
                    #pragma unroll
                    for (int p = 0; p < 2; p++)
                        mma16816(acc[mt][ntg * 2 + p], fA[mt], &fB[p * 2]);
            }
        }
        __syncthreads();
        if (c < 3) {
            stsa();
            __syncthreads();
        }
    }

    // ---- xw fragments -> smem ----
    const int fr = lane >> 2, fc = (lane & 3) * 2;
    #pragma unroll
    for (int mt = 0; mt < 2; mt++)
        #pragma unroll
        for (int nt = 0; nt < 4; nt++) {
            int col = wn + nt * 8 + fc;
            int r0 = wm + mt * 16 + fr;
            *(float2*)(xw_s + r0 * 68 + col)       = make_float2(acc[mt][nt][0], acc[mt][nt][1]);
            *(float2*)(xw_s + (r0 + 8) * 68 + col) = make_float2(acc[mt][nt][2], acc[mt][nt][3]);
        }

    // ---- edges: degree ----
    int rr_[4], cc_[4];
    #pragma unroll
    for (int i = 0; i < 4; i++) {
        int eidx = t + i * 256;
        int el = eidx >> 7, e = eidx & 127;
        rr_[i] = ei[(size_t)(e0 + el) * 256 + e];
        cc_[i] = ei[(size_t)(e0 + el) * 256 + 128 + e];
    }
    __syncthreads();
    #pragma unroll
    for (int i = 0; i < 4; i++) {
        int el = (t + i * 256) >> 7;
        atomicAdd(&deg[el * 16 + cc_[i]], 1.0f);
    }
    __syncthreads();
    if (t < 128) dnv[t] = rsqrtf(deg[t]);
    __syncthreads();

    // ---- adjacency build ----
    #pragma unroll
    for (int i = 0; i < 4; i++) {
        int el = (t + i * 256) >> 7;
        atomicAdd(&Adj[el * 256 + cc_[i] * 16 + rr_[i]],
                  dnv[el * 16 + rr_[i]] * dnv[el * 16 + cc_[i]]);
    }
    if (t < 128) {
        int el = t >> 4, r = t & 15;
        float d = dnv[t];
        atomicAdd(&Adj[el * 256 + r * 17], d * d);
    }
    __syncthreads();

    // ---- agg = Adj @ xw + bias -> A2 cols [0,64) ----
    {
        const int j  = t & 63;
        const int cg = t >> 6;
        const float bgj = bg[j];
        #pragma unroll
        for (int el = 0; el < 8; el++) {
            float xv[NUM_AGENTS];
            #pragma unroll
            for (int r = 0; r < NUM_AGENTS; r++)
                xv[r] = xw_s[(el * 16 + r) * 68 + j];
            #pragma unroll
            for (int i = 0; i < 4; i++) {
                int c = cg * 4 + i;
                float s = 0.0f;
                const float* arow = Adj + el * 256 + c * 16;
                #pragma unroll
                for (int r = 0; r < NUM_AGENTS; r++) s += arow[r] * xv[r];
                s += bgj;
                size_t node = (size_t)(e0 + el) * 16 + c;
                g_A2[node * 128 + j] = __float2half_rn(s);
            }
        }
    }

    // ---- prev_h -> A2 cols [64,128) ----
    #pragma unroll
    for (int i = 0; i < 8; i++) {
        int idx = t + i * 256;
        int el = idx >> 8, f4 = idx & 255;
        float4 v = ((const float4*)(prev_h + (size_t)(e0 + el) * FLAT_H))[f4];
        int row = f4 >> 4, jj = (f4 & 15) * 4;
        size_t node = (size_t)(e0 + el) * 16 + row;
        __half2* ph = (__half2*)(g_A2 + node * 128 + 64 + jj);
        ph[0] = __floats2half2_rn(v.x, v.y);
        ph[1] = __floats2half2_rn(v.z, v.w);
    }
}

// ---------------------------------------------------------------------------
// GEMM2 (gates + GRU): BM=128, BN=128 (N-split over 2 CTAs), BK=32, 256 thr,
// 2 CTAs/SM, 3-stage cp.async pipeline.
// ---------------------------------------------------------------------------
#define G2_A    0
#define G2_B    10240
#define G2_STG  20480
#define G2_HS   (3 * G2_STG)                 // 61440: float[128*36] = 18432
#define G2_B2S  (G2_HS + 18432)              // 79872: float[128]
#define G2_SMEM (G2_B2S + 512)               // 80384

__global__ __launch_bounds__(256, 2) void gemm_gates(
    const float* __restrict__ prev_h,
    float* __restrict__ h_out)
{
    extern __shared__ __align__(16) char smem[];
    const uint32_t sb = smem_to_u32(smem);
    float* h_s  = (float*)(smem + G2_HS);     // stride 36
    float* b2_s = (float*)(smem + G2_B2S);

    const int t = threadIdx.x, wid = t >> 5, lane = t & 31;
    const int bn = blockIdx.x;                // 0..1 (j-half)
    const size_t bm = (size_t)blockIdx.y * 128;
    const int j0 = bn * 32;
    const int wm = (wid >> 2) * 64, wn = (wid & 3) * 32;

    const int a_m = (lane & 7) + ((lane >> 3) & 1) * 8;
    const int a_k = ((lane >> 4) & 1) * 8;
    const int b_n = (lane & 7) + ((lane >> 4) & 1) * 8;
    const int b_k = ((lane >> 3) & 1) * 8;

    auto issue = [&](int c, int s) {
        uint32_t base = sb + s * G2_STG;
        #pragma unroll
        for (int i = 0; i < 2; i++) {
            int idx = t + i * 256;
            int row = idx >> 2, q = idx & 3;
            uint32_t so = (uint32_t)(row * TS + q * 8) * 2;
            cp16(base + G2_A + so, g_A2 + (bm + row) * 128 + c * 32 + q * 8);
            cp16(base + G2_B + so, g_B2 + (size_t)(bn * 128 + row) * 128 + c * 32 + q * 8);
        }
    };

    issue(0, 0); CP_COMMIT();
    issue(1, 1); CP_COMMIT();

    // preload prev_h slice + biases (overlaps async loads)
    #pragma unroll
    for (int i = 0; i < 4; i++) {
        int idx = t + i * 256;
        int row = idx >> 3, q = idx & 7;
        float4 v = *(const float4*)(prev_h + (bm + row) * RNN_H + j0 + q * 4);
        *(float4*)(h_s + row * 36 + q * 4) = v;
    }
    if (t < 128) b2_s[t] = g_b2[bn * 128 + t];

    float acc[4][4][4];
    #pragma unroll
    for (int mt = 0; mt < 4; mt++)
        #pragma unroll
        for (int ns = 0; ns < 4; ns++)
            #pragma unroll
            for (int q = 0; q < 4; q++) acc[mt][ns][q] = 0.0f;

    for (int c = 0; c < 4; c++) {
        if (c < 3) { CP_WAIT(1); } else { CP_WAIT(0); }
        __syncthreads();

        const uint32_t base = sb + (c % 3) * G2_STG;
        #pragma unroll
        for (int kk = 0; kk < 2; kk++) {
            uint32_t fA[4][4];
            #pragma unroll
            for (int mt = 0; mt < 4; mt++) {
                uint32_t off = (uint32_t)(((wm + mt * 16 + a_m) * TS + kk * 16 + a_k) * 2);
                ldmx4(fA[mt], base + G2_A + off);
            }
            uint32_t fB[2][4];
            #pragma unroll
            for (int nt = 0; nt < 2; nt++) {
                uint32_t off = (uint32_t)(((wn + nt * 16 + b_n) * TS + kk * 16 + b_k) * 2);
                ldmx4(fB[nt], base + G2_B + off);
            }
            #pragma unroll
            for (int mt = 0; mt < 4; mt++)
                #pragma unroll
                for (int ns = 0; ns < 4; ns++)
                    mma16816(acc[mt][ns], fA[mt], &fB[ns >> 1][(ns & 1) * 2]);
        }
        if (c + 2 < 4) { issue(c + 2, (c + 2) % 3); CP_COMMIT(); }
    }
    __syncthreads();

    // ---- fused GRU elementwise ----
    const int fr = lane >> 2, fc = (lane & 3) * 2;
    #pragma unroll
    for (int mt = 0; mt < 4; mt++) {
        #pragma unroll
        for (int ns = 0; ns < 4; ns++) {
            int n = wn + ns * 8 + fc;
            float v0 = acc[mt][ns][0] + b2_s[n];
            float v1 = acc[mt][ns][1] + b2_s[n + 1];
            float v2 = acc[mt][ns][2] + b2_s[n];
            float v3 = acc[mt][ns][3] + b2_s[n + 1];
            float p0 = __shfl_xor_sync(0xFFFFFFFF, v0, 1);
            float p1 = __shfl_xor_sync(0xFFFFFFFF, v1, 1);
            float p2 = __shfl_xor_sync(0xFFFFFFFF, v2, 1);
            float p3 = __shfl_xor_sync(0xFFFFFFFF, v3, 1);
            int jl = n >> 2;
            bool is01 = ((n & 2) == 0);
            float rs, zs, nxs, nhs;
            int mrow;
            if (is01) { rs = v0; zs = v1; nxs = p0; nhs = p1; mrow = wm + mt * 16 + fr; }
            else      { rs = p2; zs = p3; nxs = v2; nhs = v3; mrow = wm + mt * 16 + fr + 8; }
            float r = sigf(rs), z = sigf(zs);
            float nn = tanhf(nxs + r * nhs);
            float hp = h_s[mrow * 36 + jl];
            h_s[mrow * 36 + jl] = (1.0f - z) * nn + z * hp;
        }
    }
    __syncthreads();

    // ---- writeout: h fp32 slice + fp16 slice ----
    #pragma unroll
    for (int i = 0; i < 4; i++) {
        int idx = t + i * 256;
        int row = idx >> 3, q = idx & 7;
        float4 v = *(const float4*)(h_s + row * 36 + q * 4);
        *(float4*)(h_out + (bm + row) * RNN_H + j0 + q * 4) = v;
    }
    #pragma unroll
    for (int i = 0; i < 2; i++) {
        int idx = t + i * 256;
        int row = idx >> 2, q = idx & 3;
        const float* hp = h_s + row * 36 + q * 8;
        __half hv[8];
        #pragma unroll
        for (int e = 0; e < 8; e++) hv[e] = __float2half_rn(hp[e]);
        *(uint4*)(g_A3 + (bm + row) * RNN_H + j0 + q * 8) = *(uint4*)hv;
    }
}

// ---------------------------------------------------------------------------
// GEMM3 — fp16, 3-stage cp.async, 2 CTAs/SM.
// ---------------------------------------------------------------------------
#define G3_A   0
#define G3_B   10240
#define G3_STG 20480
#define G3_SMEM (3 * G3_STG)
#define NCHUNK (FLAT_H / 32)

__global__ __launch_bounds__(256, 2) void gemm_mma(
    const float* __restrict__ bias, float* __restrict__ C)
{
    extern __shared__ __align__(16) char smem[];
    const uint32_t sb = smem_to_u32(smem);

    const int t = threadIdx.x, wid = t >> 5, lane = t & 31;
    const int bn = blockIdx.x * 128, bm = blockIdx.y * 128;
    const int wm = (wid >> 2) * 64, wn = (wid & 3) * 32;

    const int a_m = (lane & 7) + ((lane >> 3) & 1) * 8;
    const int a_k = ((lane >> 4) & 1) * 8;
    const int b_n = (lane & 7) + ((lane >> 4) & 1) * 8;
    const int b_k = ((lane >> 3) & 1) * 8;

    auto issue = [&](int c, int s) {
        uint32_t base = sb + s * G3_STG;
        #pragma unroll
        for (int i = 0; i < 2; i++) {
            int idx = t + i * 256;
            int row = idx >> 2, q = idx & 3;
            uint32_t so = (uint32_t)(row * TS + q * 8) * 2;
            cp16(base + G3_A + so, g_A3 + (size_t)(bm + row) * FLAT_H + c * 32 + q * 8);
            cp16(base + G3_B + so, g_B3 + (size_t)(bn + row) * FLAT_H + c * 32 + q * 8);
        }
    };

    float acc[4][4][4];
    #pragma unroll
    for (int mt = 0; mt < 4; mt++)
        #pragma unroll
        for (int ns = 0; ns < 4; ns++)
            #pragma unroll
            for (int q = 0; q < 4; q++) acc[mt][ns][q] = 0.0f;

    issue(0, 0); CP_COMMIT();
    issue(1, 1); CP_COMMIT();

    for (int c = 0; c < NCHUNK; c++) {
        if (c < NCHUNK - 1) { CP_WAIT(1); } else { CP_WAIT(0); }
        __syncthreads();

        const uint32_t base = sb + (c % 3) * G3_STG;
        #pragma unroll
        for (int kk = 0; kk < 2; kk++) {
            const int akcol = kk * 16 + a_k;
            const int bkcol = kk * 16 + b_k;
            uint32_t fA[4][4];
            #pragma unroll
            for (int mt = 0; mt < 4; mt++) {
                uint32_t off = (uint32_t)(((wm + mt * 16 + a_m) * TS + akcol) * 2);
                ldmx4(fA[mt], base + G3_A + off);
            }
            uint32_t fB[2][4];
            #pragma unroll
            for (int nt = 0; nt < 2; nt++) {
                uint32_t off = (uint32_t)(((wn + nt * 16 + b_n) * TS + bkcol) * 2);
                ldmx4(fB[nt], base + G3_B + off);
            }
            #pragma unroll
            for (int mt = 0; mt < 4; mt++)
                #pragma unroll
                for (int ns = 0; ns < 4; ns++)
                    mma16816(acc[mt][ns], fA[mt], &fB[ns >> 1][(ns & 1) * 2]);
        }
        if (c + 2 < NCHUNK) { issue(c + 2, (c + 2) % 3); CP_COMMIT(); }
    }

    const int fr = lane >> 2, fc = (lane & 3) * 2;
    #pragma unroll
    for (int mt = 0; mt < 4; mt++)
        #pragma unroll
        for (int ns = 0; ns < 4; ns++) {
            int col = bn + wn + ns * 8 + fc;
            float2 bv = *(const float2*)(bias + col);
            int r0 = bm + wm + mt * 16 + fr;
            *(float2*)(C + (size_t)r0 * OUT_DIM + col) =
                make_float2(acc[mt][ns][0] + bv.x, acc[mt][ns][1] + bv.y);
            *(float2*)(C + (size_t)(r0 + 8) * OUT_DIM + col) =
                make_float2(acc[mt][ns][2] + bv.x, acc[mt][ns][3] + bv.y);
        }
}

// ---------------------------------------------------------------------------
extern "C" void kernel_launch(void* const* d_in, const int* in_sizes, int n_in,
                              void* d_out, int out_size) {
    const float* x     = (const float*)d_in[0];
    const int*   ei    = (const int*)  d_in[1];
    const float* ph    = (const float*)d_in[2];
    const float* Wg    = (const float*)d_in[3];
    const float* bg    = (const float*)d_in[4];
    const float* W_ih  = (const float*)d_in[5];
    const float* W_hh  = (const float*)d_in[6];
    const float* b_ih  = (const float*)d_in[7];
    const float* b_hh  = (const float*)d_in[8];
    const float* W_lin = (const float*)d_in[9];
    const float* b_lin = (const float*)d_in[10];

    float* out = (float*)d_out;
    bool has_nh = (out_size >= NUM_ENVS * (OUT_DIM + FLAT_H));
    float* hdst;
    if (has_nh) {
        hdst = out + (size_t)NUM_ENVS * OUT_DIM;
    } else {
        cudaGetSymbolAddress((void**)&hdst, g_hbuf);
    }

    static bool init = false;
    if (!init) {
        cudaFuncSetAttribute(gcn_front, cudaFuncAttributeMaxDynamicSharedMemorySize,
                             F_SMEM);
        cudaFuncSetAttribute(gemm_gates, cudaFuncAttributeMaxDynamicSharedMemorySize,
                             G2_SMEM);
        cudaFuncSetAttribute(gemm_mma, cudaFuncAttributeMaxDynamicSharedMemorySize,
                             G3_SMEM);
        init = true;
    }

    pack_w_kernel<<<(PK_TOT + 255) / 256, 256>>>(Wg, W_ih, W_hh, b_ih, b_hh, W_lin);
    gcn_front<<<NNODE / 128, 256, F_SMEM>>>(x, ei, ph, bg);
    gemm_gates<<<dim3(2, NNODE / 128), 256, G2_SMEM>>>(ph, hdst);
    gemm_mma<<<dim3(OUT_DIM / 128, NUM_ENVS / 128), 256, G3_SMEM>>>(b_lin, out);
}

// round 12
// speedup vs baseline: 4.3059x; 1.0682x over previous
#include <cuda_runtime.h>
#include <cuda_fp16.h>
#include <math.h>
#include <cstdint>

#define NUM_ENVS 16384
#define NUM_AGENTS 16
#define IN_DIM 128
#define GCN_H 64
#define RNN_H 64
#define OUT_DIM 512
#define FLAT_H (NUM_AGENTS * RNN_H)      // 1024
#define NNODE ((size_t)NUM_ENVS * NUM_AGENTS)   // 262144

// ---------------- static device scratch -------------------------------------
__device__ float  g_hbuf[(size_t)NUM_ENVS * FLAT_H];
__device__ __align__(16) __half g_A2[NNODE * 128];        // [gcn | prev_h] fp16
__device__ __align__(16) __half g_A3[NNODE * RNN_H];      // h_new fp16
__device__ __align__(16) __half g_Wgt[GCN_H * IN_DIM];    // Wgcn^T fp16
__device__ __align__(16) __half g_B2[256 * 128];          // gate weights fp16
__device__ float g_b2[256];
__device__ __align__(16) __half g_B3[(size_t)OUT_DIM * FLAT_H];

// ---------------- helpers ---------------------------------------------------
__device__ __forceinline__ uint32_t smem_to_u32(const void* p) {
    uint32_t a;
    asm("{ .reg .u64 t; cvta.to.shared.u64 t, %1; cvt.u32.u64 %0, t; }" : "=r"(a) : "l"(p));
    return a;
}
// fast, saturation-safe activations (MUFU.EX2 path)
__device__ __forceinline__ float sig_fast(float v) {
    return __fdividef(1.0f, 1.0f + __expf(-v));          // v->+inf: 1, v->-inf: 0
}
__device__ __forceinline__ float tanh_fast(float v) {
    float e = __expf(2.0f * v);
    return 1.0f - __fdividef(2.0f, e + 1.0f);            // e->inf: 1, e->0: -1
}

__device__ __forceinline__ void ldmx4(uint32_t* r, uint32_t addr) {
    asm volatile("ldmatrix.sync.aligned.m8n8.x4.shared.b16 {%0,%1,%2,%3}, [%4];"
                 : "=r"(r[0]), "=r"(r[1]), "=r"(r[2]), "=r"(r[3]) : "r"(addr));
}
__device__ __forceinline__ void mma16816(float* d, const uint32_t* a, const uint32_t* b) {
    asm volatile("mma.sync.aligned.m16n8k16.row.col.f32.f16.f16.f32 "
                 "{%0,%1,%2,%3}, {%4,%5,%6,%7}, {%8,%9}, {%0,%1,%2,%3};"
                 : "+f"(d[0]), "+f"(d[1]), "+f"(d[2]), "+f"(d[3])
                 : "r"(a[0]), "r"(a[1]), "r"(a[2]), "r"(a[3]), "r"(b[0]), "r"(b[1]));
}
__device__ __forceinline__ void cp16(uint32_t dst, const void* src) {
    asm volatile("cp.async.cg.shared.global [%0], [%1], 16;" :: "r"(dst), "l"(src));
}
#define CP_COMMIT() asm volatile("cp.async.commit_group;")
#define CP_WAIT(N)  asm volatile("cp.async.wait_group %0;" :: "n"(N))

// ---------------------------------------------------------------------------
// pack weights (fp16)
// ---------------------------------------------------------------------------
#define PK_WGT (GCN_H * IN_DIM)
#define PK_B2  (256 * 128)
#define PK_WL  (OUT_DIM * FLAT_H)
#define PK_TOT (PK_WGT + PK_B2 + 256 + PK_WL)

__global__ void pack_w_kernel(const float* __restrict__ Wg,
                              const float* __restrict__ W_ih,
                              const float* __restrict__ W_hh,
                              const float* __restrict__ b_ih,
                              const float* __restrict__ b_hh,
                              const float* __restrict__ Wl) {
    int idx = blockIdx.x * 256 + threadIdx.x;
    if (idx < PK_WGT) {
        int n = idx >> 7, k = idx & 127;
        g_Wgt[idx] = __float2half_rn(Wg[k * GCN_H + n]);
    } else if (idx < PK_WGT + PK_B2) {
        int r = idx - PK_WGT;
        int n = r >> 7, k = r & 127;
        int j = n >> 2, g = n & 3;
        float w = 0.0f;
        if (g == 0)      w = (k < 64) ? W_ih[j * 64 + k]         : W_hh[j * 64 + (k - 64)];
        else if (g == 1) w = (k < 64) ? W_ih[(64 + j) * 64 + k]  : W_hh[(64 + j) * 64 + (k - 64)];
        else if (g == 2) w = (k < 64) ? W_ih[(128 + j) * 64 + k] : 0.0f;
        else             w = (k < 64) ? 0.0f                     : W_hh[(128 + j) * 64 + (k - 64)];
        g_B2[r] = __float2half_rn(w);
    } else if (idx < PK_WGT + PK_B2 + 256) {
        int n = idx - PK_WGT - PK_B2;
        int j = n >> 2, g = n & 3;
        float b;
        if (g == 0)      b = b_ih[j] + b_hh[j];
        else if (g == 1) b = b_ih[64 + j] + b_hh[64 + j];
        else if (g == 2) b = b_ih[128 + j];
        else             b = b_hh[128 + j];
        g_b2[n] = b;
    } else if (idx < PK_TOT) {
        int r = idx - PK_WGT - PK_B2 - 256;
        g_B3[r] = __float2half_rn(Wl[r]);
    }
}

// ---------------------------------------------------------------------------
// gcn_front (unchanged from R11, proven)
// ---------------------------------------------------------------------------
#define TS 40
#define F_SB4  0
#define F_SA   20480
#define F_XW   30720
#define F_ADJ  65536
#define F_DEG  73728
#define F_DNV  74240
#define F_SMEM 74752

__global__ __launch_bounds__(256, 2) void gcn_front(
    const float* __restrict__ x, const int* __restrict__ ei,
    const float* __restrict__ prev_h, const float* __restrict__ bg)
{
    extern __shared__ __align__(16) char smem[];
    __half* sA   = (__half*)(smem + F_SA);
    float*  xw_s = (float*)(smem + F_XW);
    float*  Adj  = (float*)(smem + F_ADJ);
    float*  deg  = (float*)(smem + F_DEG);
    float*  dnv  = (float*)(smem + F_DNV);

    const int t = threadIdx.x, wid = t >> 5, lane = t & 31;
    const size_t bm = (size_t)blockIdx.x * 128;
    const int e0 = blockIdx.x * 8;
    const int wm = (wid >> 1) * 32, wn = (wid & 1) * 32;
    const uint32_t sb = smem_to_u32(smem);
    const uint32_t ab = sb + F_SA;

    const int a_m = (lane & 7) + ((lane >> 3) & 1) * 8;
    const int a_k = ((lane >> 4) & 1) * 8;
    const int b_n = (lane & 7) + ((lane >> 4) & 1) * 8;
    const int b_k = ((lane >> 3) & 1) * 8;

    {
        int row = t >> 2, q = t & 3;
        #pragma unroll
        for (int c = 0; c < 4; c++)
            cp16(sb + F_SB4 + (uint32_t)c * 5120 + (uint32_t)(row * TS + q * 8) * 2,
                 g_Wgt + row * 128 + c * 32 + q * 8);
        CP_COMMIT();
    }

    #pragma unroll
    for (int i = 0; i < 8; i++) Adj[t + i * 256] = 0.0f;
    if (t < 128) deg[t] = 1.0f;

    float4 pax[4];
    auto lda = [&](int c) {
        #pragma unroll
        for (int i = 0; i < 4; i++) {
            int idx = t + i * 256;
            int row = idx >> 3, q = idx & 7;
            pax[i] = *(const float4*)(x + (bm + row) * IN_DIM + c * 32 + q * 4);
        }
    };
    auto stsa = [&]() {
        #pragma unroll
        for (int i = 0; i < 4; i++) {
            int idx = t + i * 256;
            int row = idx >> 3, q = idx & 7;
            __half2* ph = (__half2*)(sA + row * TS + q * 4);
            ph[0] = __floats2half2_rn(pax[i].x, pax[i].y);
            ph[1] = __floats2half2_rn(pax[i].z, pax[i].w);
        }
    };

    float acc[2][4][4];
    #pragma unroll
    for (int mt = 0; mt < 2; mt++)
        #pragma unroll
        for (int nt = 0; nt < 4; nt++)
            #pragma unroll
            for (int q = 0; q < 4; q++) acc[mt][nt][q] = 0.0f;

    lda(0);
    stsa();
    CP_WAIT(0);
    __syncthreads();

    for (int c = 0; c < 4; c++) {
        if (c < 3) lda(c + 1);

        const uint32_t bbc = sb + F_SB4 + (uint32_t)c * 5120;
        #pragma unroll
        for (int kk = 0; kk < 2; kk++) {
            uint32_t fA[2][4];
            #pragma unroll
            for (int mt = 0; mt < 2; mt++) {
                uint32_t off = (uint32_t)(((wm + mt * 16 + a_m) * TS + kk * 16 + a_k) * 2);
                ldmx4(fA[mt], ab + off);
            }
            #pragma unroll
            for (int ntg = 0; ntg < 2; ntg++) {
                uint32_t fB[4];
                uint32_t off = (uint32_t)(((wn + ntg * 16 + b_n) * TS + kk * 16 + b_k) * 2);
                ldmx4(fB, bbc + off);
                #pragma unroll
                for (int mt = 0; mt < 2; mt++)
                    #pragma unroll
                    for (int p = 0; p < 2; p++)
                        mma16816(acc[mt][ntg * 2 + p], fA[mt], &fB[p * 2]);
            }
        }
        __syncthreads();
        if (c < 3) {
            stsa();
            __syncthreads();
        }
    }

    const int fr = lane >> 2, fc = (lane & 3) * 2;
    #pragma unroll
    for (int mt = 0; mt < 2; mt++)
        #pragma unroll
        for (int nt = 0; nt < 4; nt++) {
            int col = wn + nt * 8 + fc;
            int r0 = wm + mt * 16 + fr;
            *(float2*)(xw_s + r0 * 68 + col)       = make_float2(acc[mt][nt][0], acc[mt][nt][1]);
            *(float2*)(xw_s + (r0 + 8) * 68 + col) = make_float2(acc[mt][nt][2], acc[mt][nt][3]);
        }

    int rr_[4], cc_[4];
    #pragma unroll
    for (int i = 0; i < 4; i++) {
        int eidx = t + i * 256;
        int el = eidx >> 7, e = eidx & 127;
        rr_[i] = ei[(size_t)(e0 + el) * 256 + e];
        cc_[i] = ei[(size_t)(e0 + el) * 256 + 128 + e];
    }
    __syncthreads();
    #pragma unroll
    for (int i = 0; i < 4; i++) {
        int el = (t + i * 256) >> 7;
        atomicAdd(&deg[el * 16 + cc_[i]], 1.0f);
    }
    __syncthreads();
    if (t < 128) dnv[t] = rsqrtf(deg[t]);
    __syncthreads();

    #pragma unroll
    for (int i = 0; i < 4; i++) {
        int el = (t + i * 256) >> 7;
        atomicAdd(&Adj[el * 256 + cc_[i] * 16 + rr_[i]],
                  dnv[el * 16 + rr_[i]] * dnv[el * 16 + cc_[i]]);
    }
    if (t < 128) {
        int el = t >> 4, r = t & 15;
        float d = dnv[t];
        atomicAdd(&Adj[el * 256 + r * 17], d * d);
    }
    __syncthreads();

    {
        const int j  = t & 63;
        const int cg = t >> 6;
        const float bgj = bg[j];
        #pragma unroll
        for (int el = 0; el < 8; el++) {
            float xv[NUM_AGENTS];
            #pragma unroll
            for (int r = 0; r < NUM_AGENTS; r++)
                xv[r] = xw_s[(el * 16 + r) * 68 + j];
            #pragma unroll
            for (int i = 0; i < 4; i++) {
                int c = cg * 4 + i;
                float s = 0.0f;
                const float* arow = Adj + el * 256 + c * 16;
                #pragma unroll
                for (int r = 0; r < NUM_AGENTS; r++) s += arow[r] * xv[r];
                s += bgj;
                size_t node = (size_t)(e0 + el) * 16 + c;
                g_A2[node * 128 + j] = __float2half_rn(s);
            }
        }
    }

    #pragma unroll
    for (int i = 0; i < 8; i++) {
        int idx = t + i * 256;
        int el = idx >> 8, f4 = idx & 255;
        float4 v = ((const float4*)(prev_h + (size_t)(e0 + el) * FLAT_H))[f4];
        int row = f4 >> 4, jj = (f4 & 15) * 4;
        size_t node = (size_t)(e0 + el) * 16 + row;
        __half2* ph = (__half2*)(g_A2 + node * 128 + 64 + jj);
        ph[0] = __floats2half2_rn(v.x, v.y);
        ph[1] = __floats2half2_rn(v.z, v.w);
    }
}

// ---------------------------------------------------------------------------
// GEMM2 (gates + GRU): persistent over M_ITERS m-tiles per CTA.
// BN=128 (N-split over 2 CTAs), BK=32, 256 thr, 2 CTAs/SM.
// B2 slice resident in smem (loaded once); A 3-buffer cp.async ring.
// ---------------------------------------------------------------------------
#define M_ITERS 4
#define G2_B0   0                            // B slice: 4 x 10240 = 40960
#define G2_A0   40960                        // A ring: 3 x 10240 = 30720
#define G2_HS   71680                        // float[128*36] = 18432
#define G2_B2S  90112                        // float[128]
#define G2_SMEM 90624

__global__ __launch_bounds__(256, 2) void gemm_gates(
    const float* __restrict__ prev_h,
    float* __restrict__ h_out)
{
    extern __shared__ __align__(16) char smem[];
    const uint32_t sb = smem_to_u32(smem);
    float* h_s  = (float*)(smem + G2_HS);     // stride 36
    float* b2_s = (float*)(smem + G2_B2S);

    const int t = threadIdx.x, wid = t >> 5, lane = t & 31;
    const int bn = blockIdx.x;                // 0..1 (j-half)
    const size_t tile0 = (size_t)blockIdx.y * M_ITERS;
    const int j0 = bn * 32;
    const int wm = (wid >> 2) * 64, wn = (wid & 3) * 32;

    const int a_m = (lane & 7) + ((lane >> 3) & 1) * 8;
    const int a_k = ((lane >> 4) & 1) * 8;
    const int b_n = (lane & 7) + ((lane >> 4) & 1) * 8;
    const int b_k = ((lane >> 3) & 1) * 8;

    // ---- load entire B2 slice once (group 0) ----
    {
        #pragma unroll
        for (int c = 0; c < 4; c++)
            #pragma unroll
            for (int i = 0; i < 2; i++) {
                int idx = t + i * 256;
                int row = idx >> 2, q = idx & 3;
                cp16(sb + G2_B0 + (uint32_t)c * 10240 + (uint32_t)(row * TS + q * 8) * 2,
                     g_B2 + (size_t)(bn * 128 + row) * 128 + c * 32 + q * 8);
            }
        CP_COMMIT();
    }

    // A chunk issue: global chunk g (tile g>>2, k-chunk g&3), ring slot g%3
    auto issueA = [&](int g) {
        int mt_ = g >> 2, cc = g & 3;
        size_t bm = (tile0 + mt_) * 128;
        uint32_t base = sb + G2_A0 + (uint32_t)(g % 3) * 10240;
        #pragma unroll
        for (int i = 0; i < 2; i++) {
            int idx = t + i * 256;
            int row = idx >> 2, q = idx & 3;
            cp16(base + (uint32_t)(row * TS + q * 8) * 2,
                 g_A2 + (bm + row) * 128 + cc * 32 + q * 8);
        }
        CP_COMMIT();
    };

    issueA(0);
    issueA(1);
    if (t < 128) b2_s[t] = g_b2[bn * 128 + t];

    const int NG = M_ITERS * 4;               // 16 global chunks
    const int fr = lane >> 2, fc = (lane & 3) * 2;

    for (int m = 0; m < M_ITERS; m++) {
        const size_t bm = (tile0 + m) * 128;

        // preload prev_h slice for this tile (consumed at epilogue; the
        // chunk-loop __syncthreads make it visible)
        #pragma unroll
        for (int i = 0; i < 4; i++) {
            int idx = t + i * 256;
            int row = idx >> 3, q = idx & 7;
            float4 v = *(const float4*)(prev_h + (bm + row) * RNN_H + j0 + q * 4);
            *(float4*)(h_s + row * 36 + q * 4) = v;
        }

        float acc[4][4][4];
        #pragma unroll
        for (int mt = 0; mt < 4; mt++)
            #pragma unroll
            for (int ns = 0; ns < 4; ns++)
                #pragma unroll
                for (int q = 0; q < 4; q++) acc[mt][ns][q] = 0.0f;

        for (int cl = 0; cl < 4; cl++) {
            const int g = m * 4 + cl;
            if (g < NG - 1) { CP_WAIT(1); } else { CP_WAIT(0); }
            __syncthreads();

            const uint32_t abase = sb + G2_A0 + (uint32_t)(g % 3) * 10240;
            const uint32_t bbase = sb + G2_B0 + (uint32_t)cl * 10240;
            #pragma unroll
            for (int kk = 0; kk < 2; kk++) {
                uint32_t fA[4][4];
                #pragma unroll
                for (int mt = 0; mt < 4; mt++) {
                    uint32_t off = (uint32_t)(((wm + mt * 16 + a_m) * TS + kk * 16 + a_k) * 2);
                    ldmx4(fA[mt], abase + off);
                }
                uint32_t fB[2][4];
                #pragma unroll
                for (int nt = 0; nt < 2; nt++) {
                    uint32_t off = (uint32_t)(((wn + nt * 16 + b_n) * TS + kk * 16 + b_k) * 2);
                    ldmx4(fB[nt], bbase + off);
                }
                #pragma unroll
                for (int mt = 0; mt < 4; mt++)
                    #pragma unroll
                    for (int ns = 0; ns < 4; ns++)
                        mma16816(acc[mt][ns], fA[mt], &fB[ns >> 1][(ns & 1) * 2]);
            }
            if (g + 2 < NG) issueA(g + 2);
        }

        // ---- fused GRU elementwise (fast activations) ----
        #pragma unroll
        for (int mt = 0; mt < 4; mt++) {
            #pragma unroll
            for (int ns = 0; ns < 4; ns++) {
                int n = wn + ns * 8 + fc;
                float v0 = acc[mt][ns][0] + b2_s[n];
                float v1 = acc[mt][ns][1] + b2_s[n + 1];
                float v2 = acc[mt][ns][2] + b2_s[n];
                float v3 = acc[mt][ns][3] + b2_s[n + 1];
                float p0 = __shfl_xor_sync(0xFFFFFFFF, v0, 1);
                float p1 = __shfl_xor_sync(0xFFFFFFFF, v1, 1);
                float p2 = __shfl_xor_sync(0xFFFFFFFF, v2, 1);
                float p3 = __shfl_xor_sync(0xFFFFFFFF, v3, 1);
                int jl = n >> 2;
                bool is01 = ((n & 2) == 0);
                float rs, zs, nxs, nhs;
                int mrow;
                if (is01) { rs = v0; zs = v1; nxs = p0; nhs = p1; mrow = wm + mt * 16 + fr; }
                else      { rs = p2; zs = p3; nxs = v2; nhs = v3; mrow = wm + mt * 16 + fr + 8; }
                float r = sig_fast(rs), z = sig_fast(zs);
                float nn = tanh_fast(nxs + r * nhs);
                float hp = h_s[mrow * 36 + jl];
                h_s[mrow * 36 + jl] = (1.0f - z) * nn + z * hp;
            }
        }
        __syncthreads();

        // ---- writeout: h fp32 slice + fp16 slice ----
        #pragma unroll
        for (int i = 0; i < 4; i++) {
            int idx = t + i * 256;
            int row = idx >> 3, q = idx & 7;
            float4 v = *(const float4*)(h_s + row * 36 + q * 4);
            *(float4*)(h_out + (bm + row) * RNN_H + j0 + q * 4) = v;
        }
        #pragma unroll
        for (int i = 0; i < 2; i++) {
            int idx = t + i * 256;
            int row = idx >> 2, q = idx & 3;
            const float* hp = h_s + row * 36 + q * 8;
            __half hv[8];
            #pragma unroll
            for (int e = 0; e < 8; e++) hv[e] = __float2half_rn(hp[e]);
            *(uint4*)(g_A3 + (bm + row) * RNN_H + j0 + q * 8) = *(uint4*)hv;
        }
        __syncthreads();   // protect h_s before next tile's preload
    }
}

// ---------------------------------------------------------------------------
// GEMM3 — unchanged from R11 (proven): fp16, 3-stage cp.async, 2 CTAs/SM.
// ---------------------------------------------------------------------------
#define G3_A   0
#define G3_B   10240
#define G3_STG 20480
#define G3_SMEM (3 * G3_STG)
#define NCHUNK (FLAT_H / 32)

__global__ __launch_bounds__(256, 2) void gemm_mma(
    const float* __restrict__ bias, float* __restrict__ C)
{
    extern __shared__ __align__(16) char smem[];
    const uint32_t sb = smem_to_u32(smem);

    const int t = threadIdx.x, wid = t >> 5, lane = t & 31;
    const int bn = blockIdx.x * 128, bm = blockIdx.y * 128;
    const int wm = (wid >> 2) * 64, wn = (wid & 3) * 32;

    const int a_m = (lane & 7) + ((lane >> 3) & 1) * 8;
    const int a_k = ((lane >> 4) & 1) * 8;
    const int b_n = (lane & 7) + ((lane >> 4) & 1) * 8;
    const int b_k = ((lane >> 3) & 1) * 8;

    auto issue = [&](int c, int s) {
        uint32_t base = sb + s * G3_STG;
        #pragma unroll
        for (int i = 0; i < 2; i++) {
            int idx = t + i * 256;
            int row = idx >> 2, q = idx & 3;
            uint32_t so = (uint32_t)(row * TS + q * 8) * 2;
            cp16(base + G3_A + so, g_A3 + (size_t)(bm + row) * FLAT_H + c * 32 + q * 8);
            cp16(base + G3_B + so, g_B3 + (size_t)(bn + row) * FLAT_H + c * 32 + q * 8);
        }
    };

    float acc[4][4][4];
    #pragma unroll
    for (int mt = 0; mt < 4; mt++)
        #pragma unroll
        for (int ns = 0; ns < 4; ns++)
            #pragma unroll
            for (int q = 0; q < 4; q++) acc[mt][ns][q] = 0.0f;

    issue(0, 0); CP_COMMIT();
    issue(1, 1); CP_COMMIT();

    for (int c = 0; c < NCHUNK; c++) {
        if (c < NCHUNK - 1) { CP_WAIT(1); } else { CP_WAIT(0); }
        __syncthreads();

        const uint32_t base = sb + (c % 3) * G3_STG;
        #pragma unroll
        for (int kk = 0; kk < 2; kk++) {
            const int akcol = kk * 16 + a_k;
            const int bkcol = kk * 16 + b_k;
            uint32_t fA[4][4];
            #pragma unroll
            for (int mt = 0; mt < 4; mt++) {
                uint32_t off = (uint32_t)(((wm + mt * 16 + a_m) * TS + akcol) * 2);
                ldmx4(fA[mt], base + G3_A + off);
            }
            uint32_t fB[2][4];
            #pragma unroll
            for (int nt = 0; nt < 2; nt++) {
                uint32_t off = (uint32_t)(((wn + nt * 16 + b_n) * TS + bkcol) * 2);
                ldmx4(fB[nt], base + G3_B + off);
            }
            #pragma unroll
            for (int mt = 0; mt < 4; mt++)
                #pragma unroll
                for (int ns = 0; ns < 4; ns++)
                    mma16816(acc[mt][ns], fA[mt], &fB[ns >> 1][(ns & 1) * 2]);
        }
        if (c + 2 < NCHUNK) { issue(c + 2, (c + 2) % 3); CP_COMMIT(); }
    }

    const int fr = lane >> 2, fc = (lane & 3) * 2;
    #pragma unroll
    for (int mt = 0; mt < 4; mt++)
        #pragma unroll
        for (int ns = 0; ns < 4; ns++) {
            int col = bn + wn + ns * 8 + fc;
            float2 bv = *(const float2*)(bias + col);
            int r0 = bm + wm + mt * 16 + fr;
            *(float2*)(C + (size_t)r0 * OUT_DIM + col) =
                make_float2(acc[mt][ns][0] + bv.x, acc[mt][ns][1] + bv.y);
            *(float2*)(C + (size_t)(r0 + 8) * OUT_DIM + col) =
                make_float2(acc[mt][ns][2] + bv.x, acc[mt][ns][3] + bv.y);
        }
}

// ---------------------------------------------------------------------------
extern "C" void kernel_launch(void* const* d_in, const int* in_sizes, int n_in,
                              void* d_out, int out_size) {
    const float* x     = (const float*)d_in[0];
    const int*   ei    = (const int*)  d_in[1];
    const float* ph    = (const float*)d_in[2];
    const float* Wg    = (const float*)d_in[3];
    const float* bg    = (const float*)d_in[4];
    const float* W_ih  = (const float*)d_in[5];
    const float* W_hh  = (const float*)d_in[6];
    const float* b_ih  = (const float*)d_in[7];
    const float* b_hh  = (const float*)d_in[8];
    const float* W_lin = (const float*)d_in[9];
    const float* b_lin = (const float*)d_in[10];

    float* out = (float*)d_out;
    bool has_nh = (out_size >= NUM_ENVS * (OUT_DIM + FLAT_H));
    float* hdst;
    if (has_nh) {
        hdst = out + (size_t)NUM_ENVS * OUT_DIM;
    } else {
        cudaGetSymbolAddress((void**)&hdst, g_hbuf);
    }

    static bool init = false;
    if (!init) {
        cudaFuncSetAttribute(gcn_front, cudaFuncAttributeMaxDynamicSharedMemorySize,
                             F_SMEM);
        cudaFuncSetAttribute(gemm_gates, cudaFuncAttributeMaxDynamicSharedMemorySize,
                             G2_SMEM);
        cudaFuncSetAttribute(gemm_mma, cudaFuncAttributeMaxDynamicSharedMemorySize,
                             G3_SMEM);
        init = true;
    }

    pack_w_kernel<<<(PK_TOT + 255) / 256, 256>>>(Wg, W_ih, W_hh, b_ih, b_hh, W_lin);
    gcn_front<<<NNODE / 128, 256, F_SMEM>>>(x, ei, ph, bg);
    gemm_gates<<<dim3(2, NNODE / 128 / M_ITERS), 256, G2_SMEM>>>(ph, hdst);
    gemm_mma<<<dim3(OUT_DIM / 128, NUM_ENVS / 128), 256, G3_SMEM>>>(b_lin, out);
}